// round 5
// baseline (speedup 1.0000x reference)
#include <cuda_runtime.h>
#include <math.h>
#include <stdint.h>

#define B_  2
#define T_  2048
#define D_  1024
#define H_  16
#define DK_ 64
constexpr long long OUT_ELEMS = (long long)B_ * T_ * D_;  // 4194304
constexpr float SCALE = 0.125f;

// Scratch (device globals)
__device__ float g_Q[B_*H_*T_*DK_];
__device__ float g_K[B_*H_*T_*DK_];
__device__ float g_V[B_*H_*T_*DK_];
__device__ float g_ctx[B_*T_*D_];
__device__ float g_m[B_*H_*T_];
__device__ float g_l[B_*H_*T_];

// ---------------------------------------------------------------------------
// Helpers
// ---------------------------------------------------------------------------
__device__ __forceinline__ uint32_t f2tf(float f) {
    uint32_t u;
    asm("cvt.rna.tf32.f32 %0, %1;" : "=r"(u) : "f"(f));
    return u;
}

__device__ __forceinline__ void mma_tf32(float c[4],
                                         uint32_t a0, uint32_t a1, uint32_t a2, uint32_t a3,
                                         uint32_t b0, uint32_t b1) {
    asm volatile(
        "mma.sync.aligned.m16n8k8.row.col.f32.tf32.tf32.f32 "
        "{%0,%1,%2,%3}, {%4,%5,%6,%7}, {%8,%9}, {%0,%1,%2,%3};"
        : "+f"(c[0]), "+f"(c[1]), "+f"(c[2]), "+f"(c[3])
        : "r"(a0), "r"(a1), "r"(a2), "r"(a3), "r"(b0), "r"(b1));
}

__device__ __forceinline__ void cp_async16(float* smem_dst, const float* gmem_src) {
    uint32_t s = (uint32_t)__cvta_generic_to_shared(smem_dst);
    asm volatile("cp.async.cg.shared.global [%0], [%1], 16;" :: "r"(s), "l"(gmem_src));
}
__device__ __forceinline__ void cp_commit() {
    asm volatile("cp.async.commit_group;");
}
template<int N>
__device__ __forceinline__ void cp_wait() {
    asm volatile("cp.async.wait_group %0;" :: "n"(N));
}

// ---------------------------------------------------------------------------
// Projection GEMM: BM=BN=128, BK=32, 128 threads = 4 warps, warp tile 64x64.
// cp.async 2-stage pipeline; A stride 36, B stride 136 (both conflict-free).
// ---------------------------------------------------------------------------
constexpr int AS_STRIDE = 36;
constexpr int BS_STRIDE = 136;
constexpr int AS_STAGE  = 128 * AS_STRIDE;   // 4608 floats
constexpr int BS_STAGE  = 32 * BS_STRIDE;    // 4352 floats
constexpr int GEMM_SMEM_BYTES = (2 * AS_STAGE + 2 * BS_STAGE) * 4;  // 71680

template<bool HEADSPLIT>
__device__ __forceinline__ void gemm_mma(const float* __restrict__ A,
                                         const float* __restrict__ W,
                                         const float* __restrict__ bias,
                                         float* __restrict__ out)
{
    extern __shared__ float gsm[];
    float* As = gsm;                  // [2][AS_STAGE]
    float* Bs = gsm + 2 * AS_STAGE;   // [2][BS_STAGE]

    const int tid  = threadIdx.x;
    const int wid  = tid >> 5;
    const int lane = tid & 31;
    const int g    = lane >> 2;
    const int t    = lane & 3;
    const int wm   = wid >> 1;        // 0..1 -> 64 rows
    const int wn   = wid & 1;         // 0..1 -> 64 cols
    const int rowBase = blockIdx.y * 128;
    const int colBase = blockIdx.x * 128;

    auto load_tiles = [&](int k0, int st) {
        float* Ad = As + st * AS_STAGE;
        float* Bd = Bs + st * BS_STAGE;
#pragma unroll
        for (int l = 0; l < 8; l++) {
            int idx = tid + l * 128;
            int r   = idx >> 3;             // 0..127
            int c4  = (idx & 7) * 4;
            cp_async16(&Ad[r * AS_STRIDE + c4],
                       &A[(size_t)(rowBase + r) * D_ + k0 + c4]);
        }
#pragma unroll
        for (int l = 0; l < 8; l++) {
            int idx = tid + l * 128;
            int r   = idx >> 5;             // 0..31
            int c4  = (idx & 31) * 4;
            cp_async16(&Bd[r * BS_STRIDE + c4],
                       &W[(size_t)(k0 + r) * D_ + colBase + c4]);
        }
    };

    float acc[4][8][4];
#pragma unroll
    for (int i = 0; i < 4; i++)
#pragma unroll
        for (int j = 0; j < 8; j++)
#pragma unroll
            for (int r = 0; r < 4; r++) acc[i][j][r] = 0.f;

    load_tiles(0, 0);
    cp_commit();

    int st = 0;
    for (int k0 = 0; k0 < D_; k0 += 32, st ^= 1) {
        if (k0 + 32 < D_) {
            load_tiles(k0 + 32, st ^ 1);
            cp_commit();
            cp_wait<1>();
        } else {
            cp_wait<0>();
        }
        __syncthreads();

        const float* Ac = As + st * AS_STAGE;
        const float* Bc = Bs + st * BS_STAGE;

#pragma unroll
        for (int kk = 0; kk < 4; kk++) {
            const int kb = kk * 8;
            uint32_t a[4][4];
#pragma unroll
            for (int mt = 0; mt < 4; mt++) {
                int m = wm * 64 + mt * 16;
                a[mt][0] = f2tf(Ac[(m + g)     * AS_STRIDE + kb + t]);
                a[mt][1] = f2tf(Ac[(m + g + 8) * AS_STRIDE + kb + t]);
                a[mt][2] = f2tf(Ac[(m + g)     * AS_STRIDE + kb + t + 4]);
                a[mt][3] = f2tf(Ac[(m + g + 8) * AS_STRIDE + kb + t + 4]);
            }
#pragma unroll
            for (int nt = 0; nt < 8; nt++) {
                int n = wn * 64 + nt * 8;
                uint32_t b0 = f2tf(Bc[(kb + t)     * BS_STRIDE + n + g]);
                uint32_t b1 = f2tf(Bc[(kb + t + 4) * BS_STRIDE + n + g]);
#pragma unroll
                for (int mt = 0; mt < 4; mt++)
                    mma_tf32(acc[mt][nt], a[mt][0], a[mt][1], a[mt][2], a[mt][3], b0, b1);
            }
        }
        __syncthreads();
    }

    // Epilogue
#pragma unroll
    for (int mt = 0; mt < 4; mt++) {
#pragma unroll
        for (int nt = 0; nt < 8; nt++) {
            int n = colBase + wn * 64 + nt * 8 + 2 * t;
            float2 bv = *(const float2*)&bias[n];
#pragma unroll
            for (int rr = 0; rr < 2; rr++) {
                int m = rowBase + wm * 64 + mt * 16 + g + rr * 8;
                float2 rv;
                rv.x = acc[mt][nt][rr * 2 + 0] + bv.x;
                rv.y = acc[mt][nt][rr * 2 + 1] + bv.y;
                if (HEADSPLIT) {
                    int b  = m >> 11;
                    int tt = m & (T_ - 1);
                    int h  = n >> 6;
                    int dk = n & 63;
                    *(float2*)&out[(((size_t)(b * H_ + h) * T_) + tt) * DK_ + dk] = rv;
                } else {
                    *(float2*)&out[(size_t)m * D_ + n] = rv;
                }
            }
        }
    }
}

__global__ __launch_bounds__(128) void qkv_kernel(
    const float* __restrict__ q_inp, const float* __restrict__ k_inp,
    const float* __restrict__ v_inp,
    const float* __restrict__ Wq, const float* __restrict__ bq,
    const float* __restrict__ Wk, const float* __restrict__ bk,
    const float* __restrict__ Wv, const float* __restrict__ bv)
{
    if (blockIdx.z == 0)      gemm_mma<true>(q_inp, Wq, bq, g_Q);
    else if (blockIdx.z == 1) gemm_mma<true>(k_inp, Wk, bk, g_K);
    else                      gemm_mma<true>(v_inp, Wv, bv, g_V);
}

__global__ __launch_bounds__(128) void outproj_kernel(
    const float* __restrict__ Wo, const float* __restrict__ bo,
    float* __restrict__ out)
{
    gemm_mma<false>(g_ctx, Wo, bo, out);
}

// ---------------------------------------------------------------------------
// Flash attention: 256 threads = 8 warps, q-tile 128, kv-tile 64.
// Warp w owns q rows [w*16, w*16+16). Single-buffered K/V via cp.async.
// Stride 72 -> conflict-free for both (8g+t) and (8t+g) access patterns.
// Smem: Qs(tf32 128x72) | Ks(f32 64x72) | Vs(f32 64x72) | Ps(tf32 128x72)
// ---------------------------------------------------------------------------
constexpr int FS = 72;
constexpr int FLASH_SMEM_BYTES = (128 * FS + 64 * FS + 64 * FS + 128 * FS) * 4;  // 110592

__global__ __launch_bounds__(256, 2) void flash_kernel()
{
    extern __shared__ float fsm[];
    uint32_t* Qs = (uint32_t*)fsm;                    // [128][FS] tf32, pre-scaled
    float*    Ks = fsm + 128 * FS;                    // [64][FS]
    float*    Vs = fsm + 192 * FS;                    // [64][FS]
    uint32_t* Ps = (uint32_t*)(fsm + 256 * FS);       // [128][FS] tf32

    const int tid  = threadIdx.x;
    const int wid  = tid >> 5;
    const int lane = tid & 31;
    const int g    = lane >> 2;
    const int t    = lane & 3;
    const int qt   = gridDim.x - 1 - blockIdx.x;      // heavy tiles first
    const int bh   = blockIdx.y;
    const int q0   = qt * 128;
    const int m0   = wid * 16;

    const float* Qg = g_Q + (size_t)bh * T_ * DK_;
    const float* Kg = g_K + (size_t)bh * T_ * DK_;
    const float* Vg = g_V + (size_t)bh * T_ * DK_;

    // Load Q tile (scaled, tf32)
#pragma unroll
    for (int l = 0; l < 8; l++) {
        int idx = tid + l * 256;
        int r   = idx >> 4;              // 0..127
        int c4  = (idx & 15) * 4;
        float4 v = *(const float4*)&Qg[(size_t)(q0 + r) * DK_ + c4];
        *(uint4*)&Qs[r * FS + c4] =
            make_uint4(f2tf(v.x * SCALE), f2tf(v.y * SCALE),
                       f2tf(v.z * SCALE), f2tf(v.w * SCALE));
    }

    float m_i[2] = {-INFINITY, -INFINITY};
    float l_i[2] = {0.f, 0.f};
    float o[8][4];
#pragma unroll
    for (int nt = 0; nt < 8; nt++)
#pragma unroll
        for (int r = 0; r < 4; r++) o[nt][r] = 0.f;

    const int nkt = 2 * qt + 2;
    for (int kt = 0; kt < nkt; kt++) {
        const int k0 = kt * 64;
        __syncthreads();   // all warps done with previous K/V (+ Qs stores iter 0)
#pragma unroll
        for (int l = 0; l < 4; l++) {
            int idx = tid + l * 256;
            int r   = idx >> 4;          // 0..63
            int c4  = (idx & 15) * 4;
            cp_async16(&Ks[r * FS + c4], &Kg[(size_t)(k0 + r) * DK_ + c4]);
            cp_async16(&Vs[r * FS + c4], &Vg[(size_t)(k0 + r) * DK_ + c4]);
        }
        cp_commit();
        cp_wait<0>();
        __syncthreads();

        // S = Q K^T  (16 q rows x 64 keys per warp)
        float sc[8][4];
#pragma unroll
        for (int nt = 0; nt < 8; nt++)
#pragma unroll
            for (int r = 0; r < 4; r++) sc[nt][r] = 0.f;
#pragma unroll
        for (int kk = 0; kk < 8; kk++) {
            const int kb = kk * 8;
            uint32_t a0 = Qs[(m0 + g)     * FS + kb + t];
            uint32_t a1 = Qs[(m0 + g + 8) * FS + kb + t];
            uint32_t a2 = Qs[(m0 + g)     * FS + kb + t + 4];
            uint32_t a3 = Qs[(m0 + g + 8) * FS + kb + t + 4];
#pragma unroll
            for (int nt = 0; nt < 8; nt++) {
                uint32_t b0 = f2tf(Ks[(nt * 8 + g) * FS + kb + t]);
                uint32_t b1 = f2tf(Ks[(nt * 8 + g) * FS + kb + t + 4]);
                mma_tf32(sc[nt], a0, a1, a2, a3, b0, b1);
            }
        }

        // Causal mask (only tiles that can cross the diagonal for this warp)
        if (k0 + 63 > q0 + m0) {
#pragma unroll
            for (int nt = 0; nt < 8; nt++)
#pragma unroll
                for (int r = 0; r < 4; r++) {
                    int row = q0 + m0 + g + (r >> 1) * 8;
                    int col = k0 + nt * 8 + 2 * t + (r & 1);
                    if (col > row) sc[nt][r] = -1e30f;
                }
        }

        // Online softmax (rows live in quads: lanes xor 1,2 share the row)
#pragma unroll
        for (int rr = 0; rr < 2; rr++) {
            float tm = -INFINITY;
#pragma unroll
            for (int nt = 0; nt < 8; nt++)
                tm = fmaxf(tm, fmaxf(sc[nt][rr * 2], sc[nt][rr * 2 + 1]));
            tm = fmaxf(tm, __shfl_xor_sync(0xffffffffu, tm, 1));
            tm = fmaxf(tm, __shfl_xor_sync(0xffffffffu, tm, 2));
            float mn   = fmaxf(m_i[rr], tm);
            float corr = __expf(m_i[rr] - mn);
            float rs = 0.f;
#pragma unroll
            for (int nt = 0; nt < 8; nt++) {
                float p0 = __expf(sc[nt][rr * 2]     - mn);
                float p1 = __expf(sc[nt][rr * 2 + 1] - mn);
                sc[nt][rr * 2]     = p0;
                sc[nt][rr * 2 + 1] = p1;
                rs += p0 + p1;
            }
            rs += __shfl_xor_sync(0xffffffffu, rs, 1);
            rs += __shfl_xor_sync(0xffffffffu, rs, 2);
            l_i[rr] = l_i[rr] * corr + rs;
            m_i[rr] = mn;
#pragma unroll
            for (int nt = 0; nt < 8; nt++) {
                o[nt][rr * 2]     *= corr;
                o[nt][rr * 2 + 1] *= corr;
            }
        }

        // P -> warp-private rows of Ps
#pragma unroll
        for (int nt = 0; nt < 8; nt++)
#pragma unroll
            for (int rr = 0; rr < 2; rr++) {
                int row = m0 + g + rr * 8;
                int col = nt * 8 + 2 * t;
                *(uint2*)&Ps[row * FS + col] =
                    make_uint2(f2tf(sc[nt][rr * 2]), f2tf(sc[nt][rr * 2 + 1]));
            }
        __syncwarp();

        // O += P @ V
#pragma unroll
        for (int kk = 0; kk < 8; kk++) {
            const int kb = kk * 8;
            uint32_t a0 = Ps[(m0 + g)     * FS + kb + t];
            uint32_t a1 = Ps[(m0 + g + 8) * FS + kb + t];
            uint32_t a2 = Ps[(m0 + g)     * FS + kb + t + 4];
            uint32_t a3 = Ps[(m0 + g + 8) * FS + kb + t + 4];
#pragma unroll
            for (int nt = 0; nt < 8; nt++) {
                uint32_t b0 = f2tf(Vs[(kb + t)     * FS + nt * 8 + g]);
                uint32_t b1 = f2tf(Vs[(kb + t + 4) * FS + nt * 8 + g]);
                mma_tf32(o[nt], a0, a1, a2, a3, b0, b1);
            }
        }
    }

    // Epilogue
    const int b_ = bh >> 4;
    const int h  = bh & 15;
#pragma unroll
    for (int rr = 0; rr < 2; rr++) {
        int   q   = q0 + m0 + g + rr * 8;
        float inv = 1.f / l_i[rr];
#pragma unroll
        for (int nt = 0; nt < 8; nt++) {
            float2 rv = make_float2(o[nt][rr * 2] * inv, o[nt][rr * 2 + 1] * inv);
            *(float2*)&g_ctx[((size_t)(b_ * T_ + q)) * D_ + h * DK_ + nt * 8 + 2 * t] = rv;
        }
        if (t == 0) {
            g_m[(size_t)bh * T_ + q] = m_i[rr];
            g_l[(size_t)bh * T_ + q] = l_i[rr];
        }
    }
}

// ---------------------------------------------------------------------------
// Attn writeout: 256 threads, q-tile 128, kv-tile 64. Recompute S, write
// exp(s-m)/l for causal tiles; zeros above diagonal.
// Smem: Qs(tf32 128x72) | Ks(tf32 64x72)
// ---------------------------------------------------------------------------
constexpr int AO_SMEM_BYTES = (128 * FS + 64 * FS) * 4;  // 55296

__global__ __launch_bounds__(256) void attn_out_kernel(float* __restrict__ attn_base)
{
    extern __shared__ float asm_[];
    uint32_t* Qs = (uint32_t*)asm_;
    uint32_t* Ks = (uint32_t*)(asm_ + 128 * FS);

    const int tid  = threadIdx.x;
    const int wid  = tid >> 5;
    const int lane = tid & 31;
    const int g    = lane >> 2;
    const int t    = lane & 3;
    const int qt   = gridDim.x - 1 - blockIdx.x;
    const int bh   = blockIdx.y;
    const int q0   = qt * 128;
    const int m0   = wid * 16;

    const float* Qg   = g_Q + (size_t)bh * T_ * DK_;
    const float* Kg   = g_K + (size_t)bh * T_ * DK_;
    float*       attn = attn_base + (size_t)bh * T_ * T_;

#pragma unroll
    for (int l = 0; l < 8; l++) {
        int idx = tid + l * 256;
        int r   = idx >> 4;
        int c4  = (idx & 15) * 4;
        float4 v = *(const float4*)&Qg[(size_t)(q0 + r) * DK_ + c4];
        *(uint4*)&Qs[r * FS + c4] =
            make_uint4(f2tf(v.x * SCALE), f2tf(v.y * SCALE),
                       f2tf(v.z * SCALE), f2tf(v.w * SCALE));
    }

    float mrow[2], linv[2];
#pragma unroll
    for (int rr = 0; rr < 2; rr++) {
        int q = q0 + m0 + g + rr * 8;
        mrow[rr] = g_m[(size_t)bh * T_ + q];
        linv[rr] = 1.f / g_l[(size_t)bh * T_ + q];
    }
    __syncthreads();

    for (int kt = 0; kt < 32; kt++) {
        const int k0 = kt * 64;
        if (k0 > q0 + 127) {
            // Fully masked: zeros (rows 128 x cols 64 per tile)
            float4 z = make_float4(0.f, 0.f, 0.f, 0.f);
#pragma unroll
            for (int l = 0; l < 8; l++) {
                int idx = tid + l * 256;
                int r   = idx >> 4;          // 0..127
                int c4  = (idx & 15) * 4;
                *(float4*)&attn[(size_t)(q0 + r) * T_ + k0 + c4] = z;
            }
            continue;
        }

        __syncthreads();
#pragma unroll
        for (int l = 0; l < 4; l++) {
            int idx = tid + l * 256;
            int r   = idx >> 4;              // 0..63
            int c4  = (idx & 15) * 4;
            float4 kv = *(const float4*)&Kg[(size_t)(k0 + r) * DK_ + c4];
            *(uint4*)&Ks[r * FS + c4] =
                make_uint4(f2tf(kv.x), f2tf(kv.y), f2tf(kv.z), f2tf(kv.w));
        }
        __syncthreads();

        float sc[8][4];
#pragma unroll
        for (int nt = 0; nt < 8; nt++)
#pragma unroll
            for (int r = 0; r < 4; r++) sc[nt][r] = 0.f;
#pragma unroll
        for (int kk = 0; kk < 8; kk++) {
            const int kb = kk * 8;
            uint32_t a0 = Qs[(m0 + g)     * FS + kb + t];
            uint32_t a1 = Qs[(m0 + g + 8) * FS + kb + t];
            uint32_t a2 = Qs[(m0 + g)     * FS + kb + t + 4];
            uint32_t a3 = Qs[(m0 + g + 8) * FS + kb + t + 4];
#pragma unroll
            for (int nt = 0; nt < 8; nt++) {
                uint32_t b0 = Ks[(nt * 8 + g) * FS + kb + t];
                uint32_t b1 = Ks[(nt * 8 + g) * FS + kb + t + 4];
                mma_tf32(sc[nt], a0, a1, a2, a3, b0, b1);
            }
        }

#pragma unroll
        for (int rr = 0; rr < 2; rr++) {
            int q = q0 + m0 + g + rr * 8;
#pragma unroll
            for (int nt = 0; nt < 8; nt++) {
                int col = k0 + nt * 8 + 2 * t;
                float p0 = (col     <= q) ? __expf(sc[nt][rr * 2]     - mrow[rr]) * linv[rr] : 0.f;
                float p1 = (col + 1 <= q) ? __expf(sc[nt][rr * 2 + 1] - mrow[rr]) * linv[rr] : 0.f;
                *(float2*)&attn[(size_t)q * T_ + col] = make_float2(p0, p1);
            }
        }
    }
}

// ---------------------------------------------------------------------------
extern "C" void kernel_launch(void* const* d_in, const int* in_sizes, int n_in,
                              void* d_out, int out_size)
{
    (void)in_sizes; (void)n_in; (void)out_size;
    const float* q_inp = (const float*)d_in[0];
    const float* k_inp = (const float*)d_in[1];
    const float* v_inp = (const float*)d_in[2];
    const float* Wq = (const float*)d_in[4];
    const float* bq = (const float*)d_in[5];
    const float* Wk = (const float*)d_in[6];
    const float* bk = (const float*)d_in[7];
    const float* Wv = (const float*)d_in[8];
    const float* bv = (const float*)d_in[9];
    const float* Wo = (const float*)d_in[10];
    const float* bo = (const float*)d_in[11];
    float* out = (float*)d_out;

    cudaFuncSetAttribute(qkv_kernel,      cudaFuncAttributeMaxDynamicSharedMemorySize, GEMM_SMEM_BYTES);
    cudaFuncSetAttribute(outproj_kernel,  cudaFuncAttributeMaxDynamicSharedMemorySize, GEMM_SMEM_BYTES);
    cudaFuncSetAttribute(flash_kernel,    cudaFuncAttributeMaxDynamicSharedMemorySize, FLASH_SMEM_BYTES);
    cudaFuncSetAttribute(attn_out_kernel, cudaFuncAttributeMaxDynamicSharedMemorySize, AO_SMEM_BYTES);

    qkv_kernel<<<dim3(8, 32, 3), 128, GEMM_SMEM_BYTES>>>(q_inp, k_inp, v_inp,
                                                         Wq, bq, Wk, bk, Wv, bv);
    flash_kernel<<<dim3(16, 32), 256, FLASH_SMEM_BYTES>>>();
    attn_out_kernel<<<dim3(16, 32), 256, AO_SMEM_BYTES>>>(out + OUT_ELEMS);
    outproj_kernel<<<dim3(8, 32), 128, GEMM_SMEM_BYTES>>>(Wo, bo, out);
}

// round 8
// speedup vs baseline: 1.0609x; 1.0609x over previous
#include <cuda_runtime.h>
#include <math.h>
#include <stdint.h>

#define B_  2
#define T_  2048
#define D_  1024
#define H_  16
#define DK_ 64
constexpr long long OUT_ELEMS = (long long)B_ * T_ * D_;  // 4194304
constexpr float SCALE = 0.125f;
constexpr int XN = B_ * T_ * D_;      // 4194304 elems per activation tensor
constexpr int WN = D_ * D_;           // 1048576 elems per weight

// Scratch (device globals)
__device__ float g_xq[XN], g_xk[XN], g_xv[XN];   // tf32-rounded inputs
__device__ float g_w[4][WN];                     // tf32-rounded weights (Wq pre-scaled)
__device__ float g_bq[D_];                       // scaled bq
__device__ float g_Q[B_*H_*T_*DK_];
__device__ float g_K[B_*H_*T_*DK_];
__device__ float g_V[B_*H_*T_*DK_];
__device__ float g_ctx[B_*T_*D_];
__device__ float g_m[B_*H_*T_];
__device__ float g_l[B_*H_*T_];

// ---------------------------------------------------------------------------
// Helpers
// ---------------------------------------------------------------------------
__device__ __forceinline__ uint32_t f2tf(float f) {
    uint32_t u;
    asm("cvt.rna.tf32.f32 %0, %1;" : "=r"(u) : "f"(f));
    return u;
}
__device__ __forceinline__ float round_tf(float f) {
    return __uint_as_float(f2tf(f));
}

__device__ __forceinline__ void mma_tf32(float c[4],
                                         uint32_t a0, uint32_t a1, uint32_t a2, uint32_t a3,
                                         uint32_t b0, uint32_t b1) {
    asm volatile(
        "mma.sync.aligned.m16n8k8.row.col.f32.tf32.tf32.f32 "
        "{%0,%1,%2,%3}, {%4,%5,%6,%7}, {%8,%9}, {%0,%1,%2,%3};"
        : "+f"(c[0]), "+f"(c[1]), "+f"(c[2]), "+f"(c[3])
        : "r"(a0), "r"(a1), "r"(a2), "r"(a3), "r"(b0), "r"(b1));
}

__device__ __forceinline__ void cp_async16(float* smem_dst, const float* gmem_src) {
    uint32_t s = (uint32_t)__cvta_generic_to_shared(smem_dst);
    asm volatile("cp.async.cg.shared.global [%0], [%1], 16;" :: "r"(s), "l"(gmem_src));
}
__device__ __forceinline__ void cp_commit() {
    asm volatile("cp.async.commit_group;");
}
template<int N>
__device__ __forceinline__ void cp_wait() {
    asm volatile("cp.async.wait_group %0;" :: "n"(N));
}

// ---------------------------------------------------------------------------
// Prep: round inputs/weights to tf32 in memory; fold SCALE into Wq / bq.
// ---------------------------------------------------------------------------
__global__ __launch_bounds__(256) void prep_x_kernel(
    const float* __restrict__ q, const float* __restrict__ k,
    const float* __restrict__ v)
{
    const float* src = (blockIdx.y == 0) ? q : (blockIdx.y == 1) ? k : v;
    float* dst = (blockIdx.y == 0) ? g_xq : (blockIdx.y == 1) ? g_xk : g_xv;
    size_t i = ((size_t)blockIdx.x * 256 + threadIdx.x) * 4;
    float4 val = *(const float4*)&src[i];
    float4 r = make_float4(round_tf(val.x), round_tf(val.y),
                           round_tf(val.z), round_tf(val.w));
    *(float4*)&dst[i] = r;
}

__global__ __launch_bounds__(256) void prep_w_kernel(
    const float* __restrict__ Wq, const float* __restrict__ Wk,
    const float* __restrict__ Wv, const float* __restrict__ Wo,
    const float* __restrict__ bq)
{
    const int z = blockIdx.y;
    const float* src = (z == 0) ? Wq : (z == 1) ? Wk : (z == 2) ? Wv : Wo;
    float* dst = g_w[z];
    const float s = (z == 0) ? SCALE : 1.0f;
    size_t i = ((size_t)blockIdx.x * 256 + threadIdx.x) * 4;
    float4 val = *(const float4*)&src[i];
    float4 r = make_float4(round_tf(val.x * s), round_tf(val.y * s),
                           round_tf(val.z * s), round_tf(val.w * s));
    *(float4*)&dst[i] = r;
    if (z == 0 && blockIdx.x == 0) {
        size_t j = (size_t)threadIdx.x * 4;   // 256 threads * 4 = 1024
        float4 b = *(const float4*)&bq[j];
        *(float4*)&g_bq[j] = make_float4(b.x * SCALE, b.y * SCALE,
                                         b.z * SCALE, b.w * SCALE);
    }
}

// ---------------------------------------------------------------------------
// Projection GEMM: BM=BN=128, BK=32, 128 threads = 4 warps, warp tile 64x64.
// cp.async 2-stage pipeline; smem holds pre-rounded tf32 bits (no cvt in loop).
// ROUND_OUT: round the result to tf32 before storing (for Q/K/V/ctx chains).
// ---------------------------------------------------------------------------
constexpr int AS_STRIDE = 36;
constexpr int BS_STRIDE = 136;
constexpr int AS_STAGE  = 128 * AS_STRIDE;
constexpr int BS_STAGE  = 32 * BS_STRIDE;
constexpr int GEMM_SMEM_BYTES = (2 * AS_STAGE + 2 * BS_STAGE) * 4;  // 71680

template<bool HEADSPLIT>
__device__ __forceinline__ void gemm_mma(const float* __restrict__ A,
                                         const float* __restrict__ W,
                                         const float* __restrict__ bias,
                                         float* __restrict__ out)
{
    extern __shared__ float gsm[];
    float* As = gsm;
    float* Bs = gsm + 2 * AS_STAGE;

    const int tid  = threadIdx.x;
    const int wid  = tid >> 5;
    const int lane = tid & 31;
    const int g    = lane >> 2;
    const int t    = lane & 3;
    const int wm   = wid >> 1;
    const int wn   = wid & 1;
    const int rowBase = blockIdx.y * 128;
    const int colBase = blockIdx.x * 128;

    auto load_tiles = [&](int k0, int st) {
        float* Ad = As + st * AS_STAGE;
        float* Bd = Bs + st * BS_STAGE;
#pragma unroll
        for (int l = 0; l < 8; l++) {
            int idx = tid + l * 128;
            int r   = idx >> 3;
            int c4  = (idx & 7) * 4;
            cp_async16(&Ad[r * AS_STRIDE + c4],
                       &A[(size_t)(rowBase + r) * D_ + k0 + c4]);
        }
#pragma unroll
        for (int l = 0; l < 8; l++) {
            int idx = tid + l * 128;
            int r   = idx >> 5;
            int c4  = (idx & 31) * 4;
            cp_async16(&Bd[r * BS_STRIDE + c4],
                       &W[(size_t)(k0 + r) * D_ + colBase + c4]);
        }
    };

    float acc[4][8][4];
#pragma unroll
    for (int i = 0; i < 4; i++)
#pragma unroll
        for (int j = 0; j < 8; j++)
#pragma unroll
            for (int r = 0; r < 4; r++) acc[i][j][r] = 0.f;

    load_tiles(0, 0);
    cp_commit();

    int st = 0;
    for (int k0 = 0; k0 < D_; k0 += 32, st ^= 1) {
        if (k0 + 32 < D_) {
            load_tiles(k0 + 32, st ^ 1);
            cp_commit();
            cp_wait<1>();
        } else {
            cp_wait<0>();
        }
        __syncthreads();

        const uint32_t* Ac = (const uint32_t*)(As + st * AS_STAGE);
        const uint32_t* Bc = (const uint32_t*)(Bs + st * BS_STAGE);

#pragma unroll
        for (int kk = 0; kk < 4; kk++) {
            const int kb = kk * 8;
            uint32_t a[4][4];
#pragma unroll
            for (int mt = 0; mt < 4; mt++) {
                int m = wm * 64 + mt * 16;
                a[mt][0] = Ac[(m + g)     * AS_STRIDE + kb + t];
                a[mt][1] = Ac[(m + g + 8) * AS_STRIDE + kb + t];
                a[mt][2] = Ac[(m + g)     * AS_STRIDE + kb + t + 4];
                a[mt][3] = Ac[(m + g + 8) * AS_STRIDE + kb + t + 4];
            }
#pragma unroll
            for (int nt = 0; nt < 8; nt++) {
                int n = wn * 64 + nt * 8;
                uint32_t b0 = Bc[(kb + t)     * BS_STRIDE + n + g];
                uint32_t b1 = Bc[(kb + t + 4) * BS_STRIDE + n + g];
#pragma unroll
                for (int mt = 0; mt < 4; mt++)
                    mma_tf32(acc[mt][nt], a[mt][0], a[mt][1], a[mt][2], a[mt][3], b0, b1);
            }
        }
        __syncthreads();
    }

    // Epilogue
#pragma unroll
    for (int mt = 0; mt < 4; mt++) {
#pragma unroll
        for (int nt = 0; nt < 8; nt++) {
            int n = colBase + wn * 64 + nt * 8 + 2 * t;
            float2 bv = *(const float2*)&bias[n];
#pragma unroll
            for (int rr = 0; rr < 2; rr++) {
                int m = rowBase + wm * 64 + mt * 16 + g + rr * 8;
                float2 rv;
                if (HEADSPLIT) {
                    // round to tf32 so downstream MMAs can consume raw bits
                    rv.x = round_tf(acc[mt][nt][rr * 2 + 0] + bv.x);
                    rv.y = round_tf(acc[mt][nt][rr * 2 + 1] + bv.y);
                    int b  = m >> 11;
                    int tt = m & (T_ - 1);
                    int h  = n >> 6;
                    int dk = n & 63;
                    *(float2*)&out[(((size_t)(b * H_ + h) * T_) + tt) * DK_ + dk] = rv;
                } else {
                    rv.x = acc[mt][nt][rr * 2 + 0] + bv.x;
                    rv.y = acc[mt][nt][rr * 2 + 1] + bv.y;
                    *(float2*)&out[(size_t)m * D_ + n] = rv;
                }
            }
        }
    }
}

__global__ __launch_bounds__(128) void qkv_kernel(
    const float* __restrict__ bk, const float* __restrict__ bv)
{
    if (blockIdx.z == 0)      gemm_mma<true>(g_xq, g_w[0], g_bq, g_Q);
    else if (blockIdx.z == 1) gemm_mma<true>(g_xk, g_w[1], bk, g_K);
    else                      gemm_mma<true>(g_xv, g_w[2], bv, g_V);
}

__global__ __launch_bounds__(128) void outproj_kernel(
    const float* __restrict__ bo, float* __restrict__ out)
{
    gemm_mma<false>(g_ctx, g_w[3], bo, out);
}

// ---------------------------------------------------------------------------
// Flash attention: 128 threads = 4 warps, q-tile 64, kv-tile 64.
// Double-buffered cp.async K/V. Stride 72 -> conflict-free for (8g+t) and
// (8t+g) patterns. Q pre-scaled + pre-rounded (raw cp.async load).
// Smem: Qs 64x72 | Ks[2] 64x72 | Vs[2] 64x72 | Ps 64x72  (110592 B)
// ---------------------------------------------------------------------------
constexpr int FS = 72;
constexpr int FT = 64 * FS;
constexpr int FLASH_SMEM_BYTES = 6 * FT * 4;  // 110592

__global__ __launch_bounds__(128) void flash_kernel()
{
    extern __shared__ float fsm[];
    float* Qs = fsm;               // [64][FS]
    float* Ks = fsm + FT;          // [2][64][FS]
    float* Vs = fsm + 3 * FT;      // [2][64][FS]
    float* Ps = fsm + 5 * FT;      // [64][FS] (tf32-rounded P)

    const int tid  = threadIdx.x;
    const int wid  = tid >> 5;
    const int lane = tid & 31;
    const int g    = lane >> 2;
    const int t    = lane & 3;
    const int qt   = gridDim.x - 1 - blockIdx.x;   // heavy tiles first
    const int bh   = blockIdx.y;
    const int q0   = qt * 64;
    const int m0   = wid * 16;

    const float* Qg = g_Q + (size_t)bh * T_ * DK_;
    const float* Kg = g_K + (size_t)bh * T_ * DK_;
    const float* Vg = g_V + (size_t)bh * T_ * DK_;

    auto load_kv = [&](int kt_, int st) {
        const float* Kp = Kg + (size_t)kt_ * 64 * DK_;
        const float* Vp = Vg + (size_t)kt_ * 64 * DK_;
        float* Kd = Ks + st * FT;
        float* Vd = Vs + st * FT;
#pragma unroll
        for (int l = 0; l < 8; l++) {
            int idx = tid + l * 128;
            int r   = idx >> 4;
            int c4  = (idx & 15) * 4;
            cp_async16(&Kd[r * FS + c4], &Kp[(size_t)r * DK_ + c4]);
            cp_async16(&Vd[r * FS + c4], &Vp[(size_t)r * DK_ + c4]);
        }
    };

    // Q tile: raw async copy (already scaled+rounded)
#pragma unroll
    for (int l = 0; l < 8; l++) {
        int idx = tid + l * 128;
        int r   = idx >> 4;
        int c4  = (idx & 15) * 4;
        cp_async16(&Qs[r * FS + c4], &Qg[(size_t)(q0 + r) * DK_ + c4]);
    }
    load_kv(0, 0);
    cp_commit();

    float m_i[2] = {-INFINITY, -INFINITY};
    float l_i[2] = {0.f, 0.f};
    float o[8][4];
#pragma unroll
    for (int nt = 0; nt < 8; nt++)
#pragma unroll
        for (int r = 0; r < 4; r++) o[nt][r] = 0.f;

    const uint32_t* Qu = (const uint32_t*)Qs;
    const uint32_t* Pu = (const uint32_t*)Ps;

    for (int kt = 0; kt <= qt; kt++) {
        const int st = kt & 1;
        const int k0 = kt * 64;

        __syncthreads();   // readers done with stage st (from 2 iters ago)
        if (kt < qt) {
            load_kv(kt + 1, st ^ 1);
            cp_commit();
            cp_wait<1>();
        } else {
            cp_wait<0>();
        }
        __syncthreads();   // stage st (and Q on iter 0) visible

        const uint32_t* Kc = (const uint32_t*)(Ks + st * FT);
        const uint32_t* Vc = (const uint32_t*)(Vs + st * FT);

        // S = Q K^T
        float sc[8][4];
#pragma unroll
        for (int nt = 0; nt < 8; nt++)
#pragma unroll
            for (int r = 0; r < 4; r++) sc[nt][r] = 0.f;
#pragma unroll
        for (int kk = 0; kk < 8; kk++) {
            const int kb = kk * 8;
            uint32_t a0 = Qu[(m0 + g)     * FS + kb + t];
            uint32_t a1 = Qu[(m0 + g + 8) * FS + kb + t];
            uint32_t a2 = Qu[(m0 + g)     * FS + kb + t + 4];
            uint32_t a3 = Qu[(m0 + g + 8) * FS + kb + t + 4];
#pragma unroll
            for (int nt = 0; nt < 8; nt++) {
                uint32_t b0 = Kc[(nt * 8 + g) * FS + kb + t];
                uint32_t b1 = Kc[(nt * 8 + g) * FS + kb + t + 4];
                mma_tf32(sc[nt], a0, a1, a2, a3, b0, b1);
            }
        }

        // Causal mask on diagonal tile
        if (kt == qt) {
#pragma unroll
            for (int nt = 0; nt < 8; nt++)
#pragma unroll
                for (int r = 0; r < 4; r++) {
                    int row = q0 + m0 + g + (r >> 1) * 8;
                    int col = k0 + nt * 8 + 2 * t + (r & 1);
                    if (col > row) sc[nt][r] = -1e30f;
                }
        }

        // Online softmax
#pragma unroll
        for (int rr = 0; rr < 2; rr++) {
            float tm = -INFINITY;
#pragma unroll
            for (int nt = 0; nt < 8; nt++)
                tm = fmaxf(tm, fmaxf(sc[nt][rr * 2], sc[nt][rr * 2 + 1]));
            tm = fmaxf(tm, __shfl_xor_sync(0xffffffffu, tm, 1));
            tm = fmaxf(tm, __shfl_xor_sync(0xffffffffu, tm, 2));
            float mn   = fmaxf(m_i[rr], tm);
            float corr = __expf(m_i[rr] - mn);
            float rs = 0.f;
#pragma unroll
            for (int nt = 0; nt < 8; nt++) {
                float p0 = __expf(sc[nt][rr * 2]     - mn);
                float p1 = __expf(sc[nt][rr * 2 + 1] - mn);
                sc[nt][rr * 2]     = p0;
                sc[nt][rr * 2 + 1] = p1;
                rs += p0 + p1;
            }
            rs += __shfl_xor_sync(0xffffffffu, rs, 1);
            rs += __shfl_xor_sync(0xffffffffu, rs, 2);
            l_i[rr] = l_i[rr] * corr + rs;
            m_i[rr] = mn;
#pragma unroll
            for (int nt = 0; nt < 8; nt++) {
                o[nt][rr * 2]     *= corr;
                o[nt][rr * 2 + 1] *= corr;
            }
        }

        // P (tf32-rounded) -> warp-private rows of Ps
#pragma unroll
        for (int nt = 0; nt < 8; nt++)
#pragma unroll
            for (int rr = 0; rr < 2; rr++) {
                int row = m0 + g + rr * 8;
                int col = nt * 8 + 2 * t;
                *(uint2*)&Ps[row * FS + col] =
                    make_uint2(f2tf(sc[nt][rr * 2]), f2tf(sc[nt][rr * 2 + 1]));
            }
        __syncwarp();

        // O += P @ V
#pragma unroll
        for (int kk = 0; kk < 8; kk++) {
            const int kb = kk * 8;
            uint32_t a0 = Pu[(m0 + g)     * FS + kb + t];
            uint32_t a1 = Pu[(m0 + g + 8) * FS + kb + t];
            uint32_t a2 = Pu[(m0 + g)     * FS + kb + t + 4];
            uint32_t a3 = Pu[(m0 + g + 8) * FS + kb + t + 4];
#pragma unroll
            for (int nt = 0; nt < 8; nt++) {
                uint32_t b0 = Vc[(kb + t)     * FS + nt * 8 + g];
                uint32_t b1 = Vc[(kb + t + 4) * FS + nt * 8 + g];
                mma_tf32(o[nt], a0, a1, a2, a3, b0, b1);
            }
        }
    }

    // Epilogue: ctx rounded to tf32 (feeds outproj A operand)
    const int b_ = bh >> 4;
    const int h  = bh & 15;
#pragma unroll
    for (int rr = 0; rr < 2; rr++) {
        int   q   = q0 + m0 + g + rr * 8;
        float inv = 1.f / l_i[rr];
#pragma unroll
        for (int nt = 0; nt < 8; nt++) {
            float2 rv = make_float2(round_tf(o[nt][rr * 2] * inv),
                                    round_tf(o[nt][rr * 2 + 1] * inv));
            *(float2*)&g_ctx[((size_t)(b_ * T_ + q)) * D_ + h * DK_ + nt * 8 + 2 * t] = rv;
        }
        if (t == 0) {
            g_m[(size_t)bh * T_ + q] = m_i[rr];
            g_l[(size_t)bh * T_ + q] = l_i[rr];
        }
    }
}

// ---------------------------------------------------------------------------
// Attn writeout: 256 threads, q-tile 128, kv-tile 64, K double-buffered.
// Masked zeros written up front; causal tiles recompute S and write probs.
// Smem: Qs 128x72 | Ks[2] 64x72  (73728 B)
// ---------------------------------------------------------------------------
constexpr int AO_SMEM_BYTES = (128 * FS + 2 * 64 * FS) * 4;  // 73728

__global__ __launch_bounds__(256) void attn_out_kernel(float* __restrict__ attn_base)
{
    extern __shared__ float asm_[];
    float* Qs = asm_;                 // [128][FS]
    float* Ks = asm_ + 128 * FS;      // [2][64][FS]

    const int tid  = threadIdx.x;
    const int wid  = tid >> 5;
    const int lane = tid & 31;
    const int g    = lane >> 2;
    const int t    = lane & 3;
    const int qt   = gridDim.x - 1 - blockIdx.x;
    const int bh   = blockIdx.y;
    const int q0   = qt * 128;
    const int m0   = wid * 16;

    const float* Qg   = g_Q + (size_t)bh * T_ * DK_;
    const float* Kg   = g_K + (size_t)bh * T_ * DK_;
    float*       attn = attn_base + (size_t)bh * T_ * T_;

    const int nct = 2 * qt + 2;       // causal kv tiles

    auto load_k = [&](int kt_, int st) {
        const float* Kp = Kg + (size_t)kt_ * 64 * DK_;
        float* Kd = Ks + st * FT;
#pragma unroll
        for (int l = 0; l < 4; l++) {
            int idx = tid + l * 256;
            int r   = idx >> 4;
            int c4  = (idx & 15) * 4;
            cp_async16(&Kd[r * FS + c4], &Kp[(size_t)r * DK_ + c4]);
        }
    };

    // Q tile raw async
#pragma unroll
    for (int l = 0; l < 8; l++) {
        int idx = tid + l * 256;
        int r   = idx >> 4;
        int c4  = (idx & 15) * 4;
        cp_async16(&Qs[r * FS + c4], &Qg[(size_t)(q0 + r) * DK_ + c4]);
    }
    load_k(0, 0);
    cp_commit();

    // Masked region zeros (cols [nct*64, 2048), rows q0..q0+127)
    {
        const int zc = T_ - nct * 64;            // zero columns
        if (zc > 0) {
            const int zc4 = zc >> 2;
            float4 z = make_float4(0.f, 0.f, 0.f, 0.f);
            for (int i = tid; i < 128 * zc4; i += 256) {
                int r  = i / zc4;
                int c4 = (i - r * zc4) * 4;
                *(float4*)&attn[(size_t)(q0 + r) * T_ + nct * 64 + c4] = z;
            }
        }
    }

    float mrow[2], linv[2];
#pragma unroll
    for (int rr = 0; rr < 2; rr++) {
        int q = q0 + m0 + g + rr * 8;
        mrow[rr] = g_m[(size_t)bh * T_ + q];
        linv[rr] = 1.f / g_l[(size_t)bh * T_ + q];
    }

    const uint32_t* Qu = (const uint32_t*)Qs;

    for (int kt = 0; kt < nct; kt++) {
        const int st = kt & 1;
        const int k0 = kt * 64;

        __syncthreads();
        if (kt + 1 < nct) {
            load_k(kt + 1, st ^ 1);
            cp_commit();
            cp_wait<1>();
        } else {
            cp_wait<0>();
        }
        __syncthreads();

        const uint32_t* Kc = (const uint32_t*)(Ks + st * FT);

        float sc[8][4];
#pragma unroll
        for (int nt = 0; nt < 8; nt++)
#pragma unroll
            for (int r = 0; r < 4; r++) sc[nt][r] = 0.f;
#pragma unroll
        for (int kk = 0; kk < 8; kk++) {
            const int kb = kk * 8;
            uint32_t a0 = Qu[(m0 + g)     * FS + kb + t];
            uint32_t a1 = Qu[(m0 + g + 8) * FS + kb + t];
            uint32_t a2 = Qu[(m0 + g)     * FS + kb + t + 4];
            uint32_t a3 = Qu[(m0 + g + 8) * FS + kb + t + 4];
#pragma unroll
            for (int nt = 0; nt < 8; nt++) {
                uint32_t b0 = Kc[(nt * 8 + g) * FS + kb + t];
                uint32_t b1 = Kc[(nt * 8 + g) * FS + kb + t + 4];
                mma_tf32(sc[nt], a0, a1, a2, a3, b0, b1);
            }
        }

#pragma unroll
        for (int rr = 0; rr < 2; rr++) {
            int q = q0 + m0 + g + rr * 8;
#pragma unroll
            for (int nt = 0; nt < 8; nt++) {
                int col = k0 + nt * 8 + 2 * t;
                float p0 = (col     <= q) ? __expf(sc[nt][rr * 2]     - mrow[rr]) * linv[rr] : 0.f;
                float p1 = (col + 1 <= q) ? __expf(sc[nt][rr * 2 + 1] - mrow[rr]) * linv[rr] : 0.f;
                *(float2*)&attn[(size_t)q * T_ + col] = make_float2(p0, p1);
            }
        }
    }
}

// ---------------------------------------------------------------------------
extern "C" void kernel_launch(void* const* d_in, const int* in_sizes, int n_in,
                              void* d_out, int out_size)
{
    (void)in_sizes; (void)n_in; (void)out_size;
    const float* q_inp = (const float*)d_in[0];
    const float* k_inp = (const float*)d_in[1];
    const float* v_inp = (const float*)d_in[2];
    const float* Wq = (const float*)d_in[4];
    const float* bq = (const float*)d_in[5];
    const float* Wk = (const float*)d_in[6];
    const float* bk = (const float*)d_in[7];
    const float* Wv = (const float*)d_in[8];
    const float* bv = (const float*)d_in[9];
    const float* Wo = (const float*)d_in[10];
    const float* bo = (const float*)d_in[11];
    float* out = (float*)d_out;

    cudaFuncSetAttribute(qkv_kernel,      cudaFuncAttributeMaxDynamicSharedMemorySize, GEMM_SMEM_BYTES);
    cudaFuncSetAttribute(outproj_kernel,  cudaFuncAttributeMaxDynamicSharedMemorySize, GEMM_SMEM_BYTES);
    cudaFuncSetAttribute(flash_kernel,    cudaFuncAttributeMaxDynamicSharedMemorySize, FLASH_SMEM_BYTES);
    cudaFuncSetAttribute(attn_out_kernel, cudaFuncAttributeMaxDynamicSharedMemorySize, AO_SMEM_BYTES);

    prep_x_kernel<<<dim3(XN / (4 * 256), 3), 256>>>(q_inp, k_inp, v_inp);
    prep_w_kernel<<<dim3(WN / (4 * 256), 4), 256>>>(Wq, Wk, Wv, Wo, bq);
    qkv_kernel<<<dim3(8, 32, 3), 128, GEMM_SMEM_BYTES>>>(bk, bv);
    flash_kernel<<<dim3(32, 32), 128, FLASH_SMEM_BYTES>>>();
    attn_out_kernel<<<dim3(16, 32), 256, AO_SMEM_BYTES>>>(out + OUT_ELEMS);
    outproj_kernel<<<dim3(8, 32), 128, GEMM_SMEM_BYTES>>>(bo, out);
}

// round 12
// speedup vs baseline: 1.1113x; 1.0475x over previous
#include <cuda_runtime.h>
#include <math.h>
#include <stdint.h>

#define B_  2
#define T_  2048
#define D_  1024
#define H_  16
#define DK_ 64
constexpr long long OUT_ELEMS = (long long)B_ * T_ * D_;  // 4194304
constexpr float SCALE = 0.125f;
constexpr int XN = B_ * T_ * D_;
constexpr int WN = D_ * D_;

// Scratch (device globals)
__device__ float g_xq[XN], g_xk[XN], g_xv[XN];   // tf32-rounded inputs
__device__ float g_w[4][WN];                     // tf32-rounded weights (Wq pre-scaled)
__device__ float g_bq[D_];                       // scaled bq
__device__ float g_Q[B_*H_*T_*DK_];
__device__ float g_K[B_*H_*T_*DK_];
__device__ float g_V[B_*H_*T_*DK_];
__device__ float g_ctx[B_*T_*D_];
__device__ float g_m[B_*H_*T_];
__device__ float g_l[B_*H_*T_];

// ---------------------------------------------------------------------------
// Helpers
// ---------------------------------------------------------------------------
__device__ __forceinline__ uint32_t f2tf(float f) {
    uint32_t u;
    asm("cvt.rna.tf32.f32 %0, %1;" : "=r"(u) : "f"(f));
    return u;
}
__device__ __forceinline__ float round_tf(float f) {
    return __uint_as_float(f2tf(f));
}

__device__ __forceinline__ void mma_tf32(float c[4],
                                         uint32_t a0, uint32_t a1, uint32_t a2, uint32_t a3,
                                         uint32_t b0, uint32_t b1) {
    asm volatile(
        "mma.sync.aligned.m16n8k8.row.col.f32.tf32.tf32.f32 "
        "{%0,%1,%2,%3}, {%4,%5,%6,%7}, {%8,%9}, {%0,%1,%2,%3};"
        : "+f"(c[0]), "+f"(c[1]), "+f"(c[2]), "+f"(c[3])
        : "r"(a0), "r"(a1), "r"(a2), "r"(a3), "r"(b0), "r"(b1));
}

__device__ __forceinline__ void cp_async16(float* smem_dst, const float* gmem_src) {
    uint32_t s = (uint32_t)__cvta_generic_to_shared(smem_dst);
    asm volatile("cp.async.cg.shared.global [%0], [%1], 16;" :: "r"(s), "l"(gmem_src));
}
__device__ __forceinline__ void cp_commit() {
    asm volatile("cp.async.commit_group;");
}
template<int N>
__device__ __forceinline__ void cp_wait() {
    asm volatile("cp.async.wait_group %0;" :: "n"(N));
}

// ---------------------------------------------------------------------------
// Prep: round inputs/weights to tf32 in memory; fold SCALE into Wq / bq.
// ---------------------------------------------------------------------------
__global__ __launch_bounds__(256) void prep_x_kernel(
    const float* __restrict__ q, const float* __restrict__ k,
    const float* __restrict__ v)
{
    const float* src = (blockIdx.y == 0) ? q : (blockIdx.y == 1) ? k : v;
    float* dst = (blockIdx.y == 0) ? g_xq : (blockIdx.y == 1) ? g_xk : g_xv;
    size_t i = ((size_t)blockIdx.x * 256 + threadIdx.x) * 4;
    float4 val = *(const float4*)&src[i];
    *(float4*)&dst[i] = make_float4(round_tf(val.x), round_tf(val.y),
                                    round_tf(val.z), round_tf(val.w));
}

__global__ __launch_bounds__(256) void prep_w_kernel(
    const float* __restrict__ Wq, const float* __restrict__ Wk,
    const float* __restrict__ Wv, const float* __restrict__ Wo,
    const float* __restrict__ bq)
{
    const int z = blockIdx.y;
    const float* src = (z == 0) ? Wq : (z == 1) ? Wk : (z == 2) ? Wv : Wo;
    float* dst = g_w[z];
    const float s = (z == 0) ? SCALE : 1.0f;
    size_t i = ((size_t)blockIdx.x * 256 + threadIdx.x) * 4;
    float4 val = *(const float4*)&src[i];
    *(float4*)&dst[i] = make_float4(round_tf(val.x * s), round_tf(val.y * s),
                                    round_tf(val.z * s), round_tf(val.w * s));
    if (z == 0 && blockIdx.x == 0) {
        size_t j = (size_t)threadIdx.x * 4;
        float4 b = *(const float4*)&bq[j];
        *(float4*)&g_bq[j] = make_float4(b.x * SCALE, b.y * SCALE,
                                         b.z * SCALE, b.w * SCALE);
    }
}

// ---------------------------------------------------------------------------
// Projection GEMM: BM=BN=128, BK=32, 128 threads, warp tile 64x64, 2-stage.
// ---------------------------------------------------------------------------
constexpr int AS_STRIDE = 36;
constexpr int BS_STRIDE = 136;
constexpr int AS_STAGE  = 128 * AS_STRIDE;
constexpr int BS_STAGE  = 32 * BS_STRIDE;
constexpr int GEMM_SMEM_BYTES = (2 * AS_STAGE + 2 * BS_STAGE) * 4;  // 71680

template<bool HEADSPLIT>
__device__ __forceinline__ void gemm_mma(const float* __restrict__ A,
                                         const float* __restrict__ W,
                                         const float* __restrict__ bias,
                                         float* __restrict__ out)
{
    extern __shared__ float gsm[];
    float* As = gsm;
    float* Bs = gsm + 2 * AS_STAGE;

    const int tid  = threadIdx.x;
    const int wid  = tid >> 5;
    const int lane = tid & 31;
    const int g    = lane >> 2;
    const int t    = lane & 3;
    const int wm   = wid >> 1;
    const int wn   = wid & 1;
    const int rowBase = blockIdx.y * 128;
    const int colBase = blockIdx.x * 128;

    auto load_tiles = [&](int k0, int st) {
        float* Ad = As + st * AS_STAGE;
        float* Bd = Bs + st * BS_STAGE;
#pragma unroll
        for (int l = 0; l < 8; l++) {
            int idx = tid + l * 128;
            int r   = idx >> 3;
            int c4  = (idx & 7) * 4;
            cp_async16(&Ad[r * AS_STRIDE + c4],
                       &A[(size_t)(rowBase + r) * D_ + k0 + c4]);
        }
#pragma unroll
        for (int l = 0; l < 8; l++) {
            int idx = tid + l * 128;
            int r   = idx >> 5;
            int c4  = (idx & 31) * 4;
            cp_async16(&Bd[r * BS_STRIDE + c4],
                       &W[(size_t)(k0 + r) * D_ + colBase + c4]);
        }
    };

    float acc[4][8][4];
#pragma unroll
    for (int i = 0; i < 4; i++)
#pragma unroll
        for (int j = 0; j < 8; j++)
#pragma unroll
            for (int r = 0; r < 4; r++) acc[i][j][r] = 0.f;

    load_tiles(0, 0);
    cp_commit();

    int st = 0;
    for (int k0 = 0; k0 < D_; k0 += 32, st ^= 1) {
        if (k0 + 32 < D_) {
            load_tiles(k0 + 32, st ^ 1);
            cp_commit();
            cp_wait<1>();
        } else {
            cp_wait<0>();
        }
        __syncthreads();

        const uint32_t* Ac = (const uint32_t*)(As + st * AS_STAGE);
        const uint32_t* Bc = (const uint32_t*)(Bs + st * BS_STAGE);

#pragma unroll
        for (int kk = 0; kk < 4; kk++) {
            const int kb = kk * 8;
            uint32_t a[4][4];
#pragma unroll
            for (int mt = 0; mt < 4; mt++) {
                int m = wm * 64 + mt * 16;
                a[mt][0] = Ac[(m + g)     * AS_STRIDE + kb + t];
                a[mt][1] = Ac[(m + g + 8) * AS_STRIDE + kb + t];
                a[mt][2] = Ac[(m + g)     * AS_STRIDE + kb + t + 4];
                a[mt][3] = Ac[(m + g + 8) * AS_STRIDE + kb + t + 4];
            }
#pragma unroll
            for (int nt = 0; nt < 8; nt++) {
                int n = wn * 64 + nt * 8;
                uint32_t b0 = Bc[(kb + t)     * BS_STRIDE + n + g];
                uint32_t b1 = Bc[(kb + t + 4) * BS_STRIDE + n + g];
#pragma unroll
                for (int mt = 0; mt < 4; mt++)
                    mma_tf32(acc[mt][nt], a[mt][0], a[mt][1], a[mt][2], a[mt][3], b0, b1);
            }
        }
        __syncthreads();
    }

#pragma unroll
    for (int mt = 0; mt < 4; mt++) {
#pragma unroll
        for (int nt = 0; nt < 8; nt++) {
            int n = colBase + wn * 64 + nt * 8 + 2 * t;
            float2 bv = *(const float2*)&bias[n];
#pragma unroll
            for (int rr = 0; rr < 2; rr++) {
                int m = rowBase + wm * 64 + mt * 16 + g + rr * 8;
                float2 rv;
                if (HEADSPLIT) {
                    rv.x = round_tf(acc[mt][nt][rr * 2 + 0] + bv.x);
                    rv.y = round_tf(acc[mt][nt][rr * 2 + 1] + bv.y);
                    int b  = m >> 11;
                    int tt = m & (T_ - 1);
                    int h  = n >> 6;
                    int dk = n & 63;
                    *(float2*)&out[(((size_t)(b * H_ + h) * T_) + tt) * DK_ + dk] = rv;
                } else {
                    rv.x = acc[mt][nt][rr * 2 + 0] + bv.x;
                    rv.y = acc[mt][nt][rr * 2 + 1] + bv.y;
                    *(float2*)&out[(size_t)m * D_ + n] = rv;
                }
            }
        }
    }
}

__global__ __launch_bounds__(128) void qkv_kernel(
    const float* __restrict__ bk, const float* __restrict__ bv)
{
    if (blockIdx.z == 0)      gemm_mma<true>(g_xq, g_w[0], g_bq, g_Q);
    else if (blockIdx.z == 1) gemm_mma<true>(g_xk, g_w[1], bk, g_K);
    else                      gemm_mma<true>(g_xv, g_w[2], bv, g_V);
}

__global__ __launch_bounds__(128) void outproj_kernel(
    const float* __restrict__ bo, float* __restrict__ out)
{
    gemm_mma<false>(g_ctx, g_w[3], bo, out);
}

// ---------------------------------------------------------------------------
// Flash attention: 256 threads = 8 warps, q-tile 128, kv-tile 64, double-
// buffered cp.async K/V. P redistributed C-frag -> A-frag via warp shuffles
// (no Ps smem, no extra syncs). Stride 72: conflict-free for all patterns.
// Smem: Qs 128x72 | Ks[2] 64x72 | Vs[2] 64x72  = 110592 B -> 2 CTAs/SM.
// ---------------------------------------------------------------------------
constexpr int FS = 72;
constexpr int FT = 64 * FS;
constexpr int FLASH_SMEM_BYTES = (128 * FS + 4 * FT) * 4;  // 110592

__global__ __launch_bounds__(256, 2) void flash_kernel()
{
    extern __shared__ float fsm[];
    float* Qs = fsm;                    // [128][FS]
    float* Ks = fsm + 128 * FS;         // [2][64][FS]
    float* Vs = fsm + 128 * FS + 2 * FT;// [2][64][FS]

    const int tid  = threadIdx.x;
    const int wid  = tid >> 5;
    const int lane = tid & 31;
    const int g    = lane >> 2;
    const int t    = lane & 3;
    const int qt   = gridDim.x - 1 - blockIdx.x;   // heavy tiles first
    const int bh   = blockIdx.y;
    const int q0   = qt * 128;
    const int m0   = wid * 16;

    const float* Qg = g_Q + (size_t)bh * T_ * DK_;
    const float* Kg = g_K + (size_t)bh * T_ * DK_;
    const float* Vg = g_V + (size_t)bh * T_ * DK_;

    auto load_kv = [&](int kt_, int st) {
        const float* Kp = Kg + (size_t)kt_ * 64 * DK_;
        const float* Vp = Vg + (size_t)kt_ * 64 * DK_;
        float* Kd = Ks + st * FT;
        float* Vd = Vs + st * FT;
#pragma unroll
        for (int l = 0; l < 4; l++) {
            int idx = tid + l * 256;
            int r   = idx >> 4;
            int c4  = (idx & 15) * 4;
            cp_async16(&Kd[r * FS + c4], &Kp[(size_t)r * DK_ + c4]);
            cp_async16(&Vd[r * FS + c4], &Vp[(size_t)r * DK_ + c4]);
        }
    };

    // Q tile: raw async copy (pre-scaled + pre-rounded)
#pragma unroll
    for (int l = 0; l < 8; l++) {
        int idx = tid + l * 256;
        int r   = idx >> 4;
        int c4  = (idx & 15) * 4;
        cp_async16(&Qs[r * FS + c4], &Qg[(size_t)(q0 + r) * DK_ + c4]);
    }
    load_kv(0, 0);
    cp_commit();

    float m_i[2] = {-INFINITY, -INFINITY};
    float l_i[2] = {0.f, 0.f};
    float o[8][4];
#pragma unroll
    for (int nt = 0; nt < 8; nt++)
#pragma unroll
        for (int r = 0; r < 4; r++) o[nt][r] = 0.f;

    const uint32_t* Qu = (const uint32_t*)Qs;
    const int nkt = 2 * qt + 2;

    for (int kt = 0; kt < nkt; kt++) {
        const int st = kt & 1;
        const int k0 = kt * 64;

        __syncthreads();   // all warps done reading stage st (2 iters ago)
        if (kt + 1 < nkt) {
            load_kv(kt + 1, st ^ 1);
            cp_commit();
            cp_wait<1>();
        } else {
            cp_wait<0>();
        }
        __syncthreads();   // stage st (and Q on iter 0) visible

        const uint32_t* Kc = (const uint32_t*)(Ks + st * FT);
        const uint32_t* Vc = (const uint32_t*)(Vs + st * FT);

        // S = Q K^T
        float sc[8][4];
#pragma unroll
        for (int nt = 0; nt < 8; nt++)
#pragma unroll
            for (int r = 0; r < 4; r++) sc[nt][r] = 0.f;
#pragma unroll
        for (int kk = 0; kk < 8; kk++) {
            const int kb = kk * 8;
            uint32_t a0 = Qu[(m0 + g)     * FS + kb + t];
            uint32_t a1 = Qu[(m0 + g + 8) * FS + kb + t];
            uint32_t a2 = Qu[(m0 + g)     * FS + kb + t + 4];
            uint32_t a3 = Qu[(m0 + g + 8) * FS + kb + t + 4];
#pragma unroll
            for (int nt = 0; nt < 8; nt++) {
                uint32_t b0 = Kc[(nt * 8 + g) * FS + kb + t];
                uint32_t b1 = Kc[(nt * 8 + g) * FS + kb + t + 4];
                mma_tf32(sc[nt], a0, a1, a2, a3, b0, b1);
            }
        }

        // Causal mask (tiles crossing this warp's diagonal or fully masked)
        if (k0 + 63 > q0 + m0) {
#pragma unroll
            for (int nt = 0; nt < 8; nt++)
#pragma unroll
                for (int r = 0; r < 4; r++) {
                    int row = q0 + m0 + g + (r >> 1) * 8;
                    int col = k0 + nt * 8 + 2 * t + (r & 1);
                    if (col > row) sc[nt][r] = -1e30f;
                }
        }

        // Online softmax
#pragma unroll
        for (int rr = 0; rr < 2; rr++) {
            float tm = -INFINITY;
#pragma unroll
            for (int nt = 0; nt < 8; nt++)
                tm = fmaxf(tm, fmaxf(sc[nt][rr * 2], sc[nt][rr * 2 + 1]));
            tm = fmaxf(tm, __shfl_xor_sync(0xffffffffu, tm, 1));
            tm = fmaxf(tm, __shfl_xor_sync(0xffffffffu, tm, 2));
            float mn   = fmaxf(m_i[rr], tm);
            float corr = __expf(m_i[rr] - mn);
            float rs = 0.f;
#pragma unroll
            for (int nt = 0; nt < 8; nt++) {
                float p0 = __expf(sc[nt][rr * 2]     - mn);
                float p1 = __expf(sc[nt][rr * 2 + 1] - mn);
                sc[nt][rr * 2]     = p0;
                sc[nt][rr * 2 + 1] = p1;
                rs += p0 + p1;
            }
            rs += __shfl_xor_sync(0xffffffffu, rs, 1);
            rs += __shfl_xor_sync(0xffffffffu, rs, 2);
            l_i[rr] = l_i[rr] * corr + rs;
            m_i[rr] = mn;
#pragma unroll
            for (int nt = 0; nt < 8; nt++) {
                o[nt][rr * 2]     *= corr;
                o[nt][rr * 2 + 1] *= corr;
            }
        }

        // Round P to tf32 in registers
#pragma unroll
        for (int nt = 0; nt < 8; nt++)
#pragma unroll
            for (int r = 0; r < 4; r++) sc[nt][r] = round_tf(sc[nt][r]);

        // O += P @ V : redistribute C-frag -> A-frag via shuffles
        const int src  = (g << 2) + (t >> 1);
        const int src2 = src + 2;
        const bool odd = (t & 1);
#pragma unroll
        for (int kk = 0; kk < 8; kk++) {
            const int kb = kk * 8;
            float p00 = __shfl_sync(0xffffffffu, sc[kk][0], src);
            float p01 = __shfl_sync(0xffffffffu, sc[kk][1], src);
            float p10 = __shfl_sync(0xffffffffu, sc[kk][2], src);
            float p11 = __shfl_sync(0xffffffffu, sc[kk][3], src);
            float q00 = __shfl_sync(0xffffffffu, sc[kk][0], src2);
            float q01 = __shfl_sync(0xffffffffu, sc[kk][1], src2);
            float q10 = __shfl_sync(0xffffffffu, sc[kk][2], src2);
            float q11 = __shfl_sync(0xffffffffu, sc[kk][3], src2);
            uint32_t a0 = __float_as_uint(odd ? p01 : p00);
            uint32_t a1 = __float_as_uint(odd ? p11 : p10);
            uint32_t a2 = __float_as_uint(odd ? q01 : q00);
            uint32_t a3 = __float_as_uint(odd ? q11 : q10);
#pragma unroll
            for (int nt = 0; nt < 8; nt++) {
                uint32_t b0 = Vc[(kb + t)     * FS + nt * 8 + g];
                uint32_t b1 = Vc[(kb + t + 4) * FS + nt * 8 + g];
                mma_tf32(o[nt], a0, a1, a2, a3, b0, b1);
            }
        }
    }

    // Epilogue: ctx rounded to tf32 (feeds outproj A operand)
    const int b_ = bh >> 4;
    const int h  = bh & 15;
#pragma unroll
    for (int rr = 0; rr < 2; rr++) {
        int   q   = q0 + m0 + g + rr * 8;
        float inv = 1.f / l_i[rr];
#pragma unroll
        for (int nt = 0; nt < 8; nt++) {
            float2 rv = make_float2(round_tf(o[nt][rr * 2] * inv),
                                    round_tf(o[nt][rr * 2 + 1] * inv));
            *(float2*)&g_ctx[((size_t)(b_ * T_ + q)) * D_ + h * DK_ + nt * 8 + 2 * t] = rv;
        }
        if (t == 0) {
            g_m[(size_t)bh * T_ + q] = m_i[rr];
            g_l[(size_t)bh * T_ + q] = l_i[rr];
        }
    }
}

// ---------------------------------------------------------------------------
// Attn writeout: 256 threads, q-tile 128, kv-tile 64, K double-buffered.
// ---------------------------------------------------------------------------
constexpr int AO_SMEM_BYTES = (128 * FS + 2 * FT) * 4;  // 73728

__global__ __launch_bounds__(256) void attn_out_kernel(float* __restrict__ attn_base)
{
    extern __shared__ float asm_[];
    float* Qs = asm_;                 // [128][FS]
    float* Ks = asm_ + 128 * FS;      // [2][64][FS]

    const int tid  = threadIdx.x;
    const int wid  = tid >> 5;
    const int lane = tid & 31;
    const int g    = lane >> 2;
    const int t    = lane & 3;
    const int qt   = gridDim.x - 1 - blockIdx.x;
    const int bh   = blockIdx.y;
    const int q0   = qt * 128;
    const int m0   = wid * 16;

    const float* Qg   = g_Q + (size_t)bh * T_ * DK_;
    const float* Kg   = g_K + (size_t)bh * T_ * DK_;
    float*       attn = attn_base + (size_t)bh * T_ * T_;

    const int nct = 2 * qt + 2;

    auto load_k = [&](int kt_, int st) {
        const float* Kp = Kg + (size_t)kt_ * 64 * DK_;
        float* Kd = Ks + st * FT;
#pragma unroll
        for (int l = 0; l < 4; l++) {
            int idx = tid + l * 256;
            int r   = idx >> 4;
            int c4  = (idx & 15) * 4;
            cp_async16(&Kd[r * FS + c4], &Kp[(size_t)r * DK_ + c4]);
        }
    };

#pragma unroll
    for (int l = 0; l < 8; l++) {
        int idx = tid + l * 256;
        int r   = idx >> 4;
        int c4  = (idx & 15) * 4;
        cp_async16(&Qs[r * FS + c4], &Qg[(size_t)(q0 + r) * DK_ + c4]);
    }
    load_k(0, 0);
    cp_commit();

    // Masked region zeros
    {
        const int zc = T_ - nct * 64;
        if (zc > 0) {
            const int zc4 = zc >> 2;
            float4 z = make_float4(0.f, 0.f, 0.f, 0.f);
            for (int i = tid; i < 128 * zc4; i += 256) {
                int r  = i / zc4;
                int c4 = (i - r * zc4) * 4;
                *(float4*)&attn[(size_t)(q0 + r) * T_ + nct * 64 + c4] = z;
            }
        }
    }

    float mrow[2], linv[2];
#pragma unroll
    for (int rr = 0; rr < 2; rr++) {
        int q = q0 + m0 + g + rr * 8;
        mrow[rr] = g_m[(size_t)bh * T_ + q];
        linv[rr] = 1.f / g_l[(size_t)bh * T_ + q];
    }

    const uint32_t* Qu = (const uint32_t*)Qs;

    for (int kt = 0; kt < nct; kt++) {
        const int st = kt & 1;
        const int k0 = kt * 64;

        __syncthreads();
        if (kt + 1 < nct) {
            load_k(kt + 1, st ^ 1);
            cp_commit();
            cp_wait<1>();
        } else {
            cp_wait<0>();
        }
        __syncthreads();

        const uint32_t* Kc = (const uint32_t*)(Ks + st * FT);

        float sc[8][4];
#pragma unroll
        for (int nt = 0; nt < 8; nt++)
#pragma unroll
            for (int r = 0; r < 4; r++) sc[nt][r] = 0.f;
#pragma unroll
        for (int kk = 0; kk < 8; kk++) {
            const int kb = kk * 8;
            uint32_t a0 = Qu[(m0 + g)     * FS + kb + t];
            uint32_t a1 = Qu[(m0 + g + 8) * FS + kb + t];
            uint32_t a2 = Qu[(m0 + g)     * FS + kb + t + 4];
            uint32_t a3 = Qu[(m0 + g + 8) * FS + kb + t + 4];
#pragma unroll
            for (int nt = 0; nt < 8; nt++) {
                uint32_t b0 = Kc[(nt * 8 + g) * FS + kb + t];
                uint32_t b1 = Kc[(nt * 8 + g) * FS + kb + t + 4];
                mma_tf32(sc[nt], a0, a1, a2, a3, b0, b1);
            }
        }

#pragma unroll
        for (int rr = 0; rr < 2; rr++) {
            int q = q0 + m0 + g + rr * 8;
#pragma unroll
            for (int nt = 0; nt < 8; nt++) {
                int col = k0 + nt * 8 + 2 * t;
                float p0 = (col     <= q) ? __expf(sc[nt][rr * 2]     - mrow[rr]) * linv[rr] : 0.f;
                float p1 = (col + 1 <= q) ? __expf(sc[nt][rr * 2 + 1] - mrow[rr]) * linv[rr] : 0.f;
                *(float2*)&attn[(size_t)q * T_ + col] = make_float2(p0, p1);
            }
        }
    }
}

// ---------------------------------------------------------------------------
extern "C" void kernel_launch(void* const* d_in, const int* in_sizes, int n_in,
                              void* d_out, int out_size)
{
    (void)in_sizes; (void)n_in; (void)out_size;
    const float* q_inp = (const float*)d_in[0];
    const float* k_inp = (const float*)d_in[1];
    const float* v_inp = (const float*)d_in[2];
    const float* Wq = (const float*)d_in[4];
    const float* bq = (const float*)d_in[5];
    const float* Wk = (const float*)d_in[6];
    const float* bk = (const float*)d_in[7];
    const float* Wv = (const float*)d_in[8];
    const float* bv = (const float*)d_in[9];
    const float* Wo = (const float*)d_in[10];
    const float* bo = (const float*)d_in[11];
    float* out = (float*)d_out;

    // Lazy one-time setup (first call is the uncaptured correctness run)
    static cudaStream_t s2 = nullptr;
    static cudaEvent_t  e1 = nullptr, e2 = nullptr;
    if (!s2) {
        cudaStreamCreateWithFlags(&s2, cudaStreamNonBlocking);
        cudaEventCreateWithFlags(&e1, cudaEventDisableTiming);
        cudaEventCreateWithFlags(&e2, cudaEventDisableTiming);
        cudaFuncSetAttribute(qkv_kernel,      cudaFuncAttributeMaxDynamicSharedMemorySize, GEMM_SMEM_BYTES);
        cudaFuncSetAttribute(outproj_kernel,  cudaFuncAttributeMaxDynamicSharedMemorySize, GEMM_SMEM_BYTES);
        cudaFuncSetAttribute(flash_kernel,    cudaFuncAttributeMaxDynamicSharedMemorySize, FLASH_SMEM_BYTES);
        cudaFuncSetAttribute(attn_out_kernel, cudaFuncAttributeMaxDynamicSharedMemorySize, AO_SMEM_BYTES);
    }

    prep_x_kernel<<<dim3(XN / (4 * 256), 3), 256>>>(q_inp, k_inp, v_inp);
    prep_w_kernel<<<dim3(WN / (4 * 256), 4), 256>>>(Wq, Wk, Wv, Wo, bq);
    qkv_kernel<<<dim3(8, 32, 3), 128, GEMM_SMEM_BYTES>>>(bk, bv);
    flash_kernel<<<dim3(16, 32), 256, FLASH_SMEM_BYTES>>>();

    // Fork: attn writeout on s2, output projection on the main stream.
    cudaEventRecord(e1, 0);
    cudaStreamWaitEvent(s2, e1, 0);
    attn_out_kernel<<<dim3(16, 32), 256, AO_SMEM_BYTES, s2>>>(out + OUT_ELEMS);
    outproj_kernel<<<dim3(8, 32), 128, GEMM_SMEM_BYTES>>>(bo, out);
    cudaEventRecord(e2, s2);
    cudaStreamWaitEvent(0, e2, 0);
}

// round 14
// speedup vs baseline: 1.3011x; 1.1708x over previous
#include <cuda_runtime.h>
#include <math.h>
#include <stdint.h>

#define B_  2
#define T_  2048
#define D_  1024
#define H_  16
#define DK_ 64
constexpr long long OUT_ELEMS = (long long)B_ * T_ * D_;  // 4194304
constexpr float SCALE = 0.125f;
constexpr int XN = B_ * T_ * D_;
constexpr int WN = D_ * D_;

// Scratch (device globals)
__device__ float g_xq[XN], g_xk[XN], g_xv[XN];   // tf32-rounded inputs
__device__ float g_w[4][WN];                     // TRANSPOSED Wt[n][k], rounded (Wq scaled)
__device__ float g_bq[D_];                       // scaled bq
__device__ float g_Q[B_*H_*T_*DK_];              // [bh][t][dk]
__device__ float g_K[B_*H_*T_*DK_];              // [bh][t][dk]
__device__ float g_Vt[B_*H_*DK_*T_];             // [bh][dk][t]  (transposed V)
__device__ float g_ctx[B_*T_*D_];
__device__ float g_m[B_*H_*T_];
__device__ float g_l[B_*H_*T_];

// ---------------------------------------------------------------------------
// Helpers
// ---------------------------------------------------------------------------
__device__ __forceinline__ uint32_t f2tf(float f) {
    uint32_t u;
    asm("cvt.rna.tf32.f32 %0, %1;" : "=r"(u) : "f"(f));
    return u;
}
__device__ __forceinline__ float round_tf(float f) {
    return __uint_as_float(f2tf(f));
}

__device__ __forceinline__ void mma_tf32(float c[4],
                                         uint32_t a0, uint32_t a1, uint32_t a2, uint32_t a3,
                                         uint32_t b0, uint32_t b1) {
    asm volatile(
        "mma.sync.aligned.m16n8k8.row.col.f32.tf32.tf32.f32 "
        "{%0,%1,%2,%3}, {%4,%5,%6,%7}, {%8,%9}, {%0,%1,%2,%3};"
        : "+f"(c[0]), "+f"(c[1]), "+f"(c[2]), "+f"(c[3])
        : "r"(a0), "r"(a1), "r"(a2), "r"(a3), "r"(b0), "r"(b1));
}

__device__ __forceinline__ void cp_async16(float* smem_dst, const float* gmem_src) {
    uint32_t s = (uint32_t)__cvta_generic_to_shared(smem_dst);
    asm volatile("cp.async.cg.shared.global [%0], [%1], 16;" :: "r"(s), "l"(gmem_src));
}
__device__ __forceinline__ void cp_commit() {
    asm volatile("cp.async.commit_group;");
}
template<int N>
__device__ __forceinline__ void cp_wait() {
    asm volatile("cp.async.wait_group %0;" :: "n"(N));
}

// ---------------------------------------------------------------------------
// Prep
// ---------------------------------------------------------------------------
__global__ __launch_bounds__(256) void prep_x_kernel(
    const float* __restrict__ q, const float* __restrict__ k,
    const float* __restrict__ v)
{
    const float* src = (blockIdx.y == 0) ? q : (blockIdx.y == 1) ? k : v;
    float* dst = (blockIdx.y == 0) ? g_xq : (blockIdx.y == 1) ? g_xk : g_xv;
    size_t i = ((size_t)blockIdx.x * 256 + threadIdx.x) * 4;
    float4 val = *(const float4*)&src[i];
    *(float4*)&dst[i] = make_float4(round_tf(val.x), round_tf(val.y),
                                    round_tf(val.z), round_tf(val.w));
}

// Transpose W [k][n] -> Wt [n][k], round to tf32, fold SCALE into Wq (+bq).
__global__ __launch_bounds__(256) void prep_w_kernel(
    const float* __restrict__ Wq, const float* __restrict__ Wk,
    const float* __restrict__ Wv, const float* __restrict__ Wo,
    const float* __restrict__ bq)
{
    __shared__ float tile[64][65];
    const int z = blockIdx.z;
    const float* src = (z == 0) ? Wq : (z == 1) ? Wk : (z == 2) ? Wv : Wo;
    float* dst = g_w[z];
    const float s = (z == 0) ? SCALE : 1.0f;
    const int k0 = blockIdx.x * 64;
    const int n0 = blockIdx.y * 64;
    const int tid = threadIdx.x;

#pragma unroll
    for (int l = 0; l < 16; l++) {
        int i  = tid + l * 256;
        int kr = i >> 6;
        int nc = i & 63;
        tile[kr][nc] = round_tf(src[(size_t)(k0 + kr) * D_ + n0 + nc] * s);
    }
    __syncthreads();
#pragma unroll
    for (int l = 0; l < 16; l++) {
        int i  = tid + l * 256;
        int nr = i >> 6;
        int kc = i & 63;
        dst[(size_t)(n0 + nr) * D_ + k0 + kc] = tile[kc][nr];
    }

    if (z == 0 && blockIdx.x == 0 && blockIdx.y == 0) {
        size_t j = (size_t)tid * 4;
        float4 b = *(const float4*)&bq[j];
        *(float4*)&g_bq[j] = make_float4(b.x * SCALE, b.y * SCALE,
                                         b.z * SCALE, b.w * SCALE);
    }
}

// ---------------------------------------------------------------------------
// Projection GEMM: BM=BN=128, BK=32, 128 threads, warp tile 64x64, 2-stage.
// A smem [m][40], B smem (from Wt) [n][40]. All fragment loads are LDS.64
// via the slot remap (t,t+4) <-> logical k (2t,2t+1).
// MODE: 0 = plain out [m][n]; 1 = headsplit [bh][t][dk]; 2 = Vt [bh][dk][t].
// ---------------------------------------------------------------------------
constexpr int GS = 40;                       // smem row stride
constexpr int G_STAGE = 128 * GS;            // 5120 floats per tile
constexpr int GEMM_SMEM_BYTES = 4 * G_STAGE * 4;  // 81920

template<int MODE>
__device__ __forceinline__ void gemm_mma(const float* __restrict__ A,
                                         const float* __restrict__ W,
                                         const float* __restrict__ bias,
                                         float* __restrict__ out)
{
    extern __shared__ float gsm[];
    float* As = gsm;                  // [2][128][GS]
    float* Bs = gsm + 2 * G_STAGE;    // [2][128][GS]

    const int tid  = threadIdx.x;
    const int wid  = tid >> 5;
    const int lane = tid & 31;
    const int g    = lane >> 2;
    const int t    = lane & 3;
    const int wm   = wid >> 1;
    const int wn   = wid & 1;
    const int rowBase = blockIdx.y * 128;
    const int colBase = blockIdx.x * 128;

    auto load_tiles = [&](int k0, int st) {
        float* Ad = As + st * G_STAGE;
        float* Bd = Bs + st * G_STAGE;
#pragma unroll
        for (int l = 0; l < 8; l++) {
            int idx = tid + l * 128;
            int r   = idx >> 3;
            int c4  = (idx & 7) * 4;
            cp_async16(&Ad[r * GS + c4], &A[(size_t)(rowBase + r) * D_ + k0 + c4]);
            cp_async16(&Bd[r * GS + c4], &W[(size_t)(colBase + r) * D_ + k0 + c4]);
        }
    };

    float acc[4][8][4];
#pragma unroll
    for (int i = 0; i < 4; i++)
#pragma unroll
        for (int j = 0; j < 8; j++)
#pragma unroll
            for (int r = 0; r < 4; r++) acc[i][j][r] = 0.f;

    load_tiles(0, 0);
    cp_commit();

    int st = 0;
    for (int k0 = 0; k0 < D_; k0 += 32, st ^= 1) {
        if (k0 + 32 < D_) {
            load_tiles(k0 + 32, st ^ 1);
            cp_commit();
            cp_wait<1>();
        } else {
            cp_wait<0>();
        }
        __syncthreads();

        const float* Ac = As + st * G_STAGE;
        const float* Bc = Bs + st * G_STAGE;

#pragma unroll
        for (int kk = 0; kk < 4; kk++) {
            const int kb = kk * 8 + 2 * t;
            uint2 aU[4][2];
#pragma unroll
            for (int mt = 0; mt < 4; mt++) {
                int m = wm * 64 + mt * 16;
                aU[mt][0] = *(const uint2*)&Ac[(m + g)     * GS + kb];
                aU[mt][1] = *(const uint2*)&Ac[(m + g + 8) * GS + kb];
            }
#pragma unroll
            for (int nt = 0; nt < 8; nt++) {
                int n = wn * 64 + nt * 8;
                uint2 bU = *(const uint2*)&Bc[(n + g) * GS + kb];
#pragma unroll
                for (int mt = 0; mt < 4; mt++)
                    mma_tf32(acc[mt][nt], aU[mt][0].x, aU[mt][1].x,
                             aU[mt][0].y, aU[mt][1].y, bU.x, bU.y);
            }
        }
        __syncthreads();
    }

    // Epilogue
#pragma unroll
    for (int mt = 0; mt < 4; mt++) {
#pragma unroll
        for (int nt = 0; nt < 8; nt++) {
            int n = colBase + wn * 64 + nt * 8 + 2 * t;
            float2 bv = *(const float2*)&bias[n];
#pragma unroll
            for (int rr = 0; rr < 2; rr++) {
                int m = rowBase + wm * 64 + mt * 16 + g + rr * 8;
                float v0 = acc[mt][nt][rr * 2 + 0] + bv.x;
                float v1 = acc[mt][nt][rr * 2 + 1] + bv.y;
                if (MODE == 0) {
                    *(float2*)&out[(size_t)m * D_ + n] = make_float2(v0, v1);
                } else {
                    int b  = m >> 11;
                    int tt = m & (T_ - 1);
                    int h  = n >> 6;
                    int dk = n & 63;
                    if (MODE == 1) {
                        *(float2*)&out[(((size_t)(b * H_ + h) * T_) + tt) * DK_ + dk] =
                            make_float2(round_tf(v0), round_tf(v1));
                    } else {  // MODE 2: Vt[bh][dk][token]
                        size_t base = ((size_t)(b * H_ + h) * DK_ + dk) * T_ + tt;
                        out[base]      = round_tf(v0);
                        out[base + T_] = round_tf(v1);
                    }
                }
            }
        }
    }
}

__global__ __launch_bounds__(128, 2) void qkv_kernel(
    const float* __restrict__ bk, const float* __restrict__ bv)
{
    if (blockIdx.z == 0)      gemm_mma<1>(g_xq, g_w[0], g_bq, g_Q);
    else if (blockIdx.z == 1) gemm_mma<1>(g_xk, g_w[1], bk, g_K);
    else                      gemm_mma<2>(g_xv, g_w[2], bv, g_Vt);
}

__global__ __launch_bounds__(128, 2) void outproj_kernel(
    const float* __restrict__ bo, float* __restrict__ out)
{
    gemm_mma<0>(g_ctx, g_w[3], bo, out);
}

// ---------------------------------------------------------------------------
// Flash attention: 256 threads = 8 warps, q-tile 128, kv-tile 64, double-
// buffered cp.async K/Vt. All fragment loads LDS.64; PV consumes the S
// C-fragment directly as its A-fragment (no shuffles, no P smem).
// Smem: Qs 128x72 | Ks[2] 64x72 | Vts[2] 64x72  = 110592 B -> 2 CTAs/SM.
// ---------------------------------------------------------------------------
constexpr int FS = 72;
constexpr int FT = 64 * FS;
constexpr int FLASH_SMEM_BYTES = (128 * FS + 4 * FT) * 4;  // 110592

__global__ __launch_bounds__(256, 2) void flash_kernel()
{
    extern __shared__ float fsm[];
    float* Qs  = fsm;                      // [128][FS]  (q rows, dk cols)
    float* Ks  = fsm + 128 * FS;           // [2][64][FS] (key rows, dk cols)
    float* Vts = fsm + 128 * FS + 2 * FT;  // [2][64][FS] (dk rows, key cols)

    const int tid  = threadIdx.x;
    const int wid  = tid >> 5;
    const int lane = tid & 31;
    const int g    = lane >> 2;
    const int t    = lane & 3;
    const int qt   = gridDim.x - 1 - blockIdx.x;   // heavy tiles first
    const int bh   = blockIdx.y;
    const int q0   = qt * 128;
    const int m0   = wid * 16;

    const float* Qg  = g_Q  + (size_t)bh * T_ * DK_;
    const float* Kg  = g_K  + (size_t)bh * T_ * DK_;
    const float* Vtg = g_Vt + (size_t)bh * DK_ * T_;

    auto load_kv = [&](int kt_, int st) {
        const int k0 = kt_ * 64;
        float* Kd = Ks  + st * FT;
        float* Vd = Vts + st * FT;
#pragma unroll
        for (int l = 0; l < 4; l++) {
            int idx = tid + l * 256;
            int r   = idx >> 4;
            int c4  = (idx & 15) * 4;
            cp_async16(&Kd[r * FS + c4], &Kg[(size_t)(k0 + r) * DK_ + c4]);
            cp_async16(&Vd[r * FS + c4], &Vtg[(size_t)r * T_ + k0 + c4]);
        }
    };

    // Q tile raw async (pre-scaled + pre-rounded)
#pragma unroll
    for (int l = 0; l < 8; l++) {
        int idx = tid + l * 256;
        int r   = idx >> 4;
        int c4  = (idx & 15) * 4;
        cp_async16(&Qs[r * FS + c4], &Qg[(size_t)(q0 + r) * DK_ + c4]);
    }
    load_kv(0, 0);
    cp_commit();

    float m_i[2] = {-INFINITY, -INFINITY};
    float l_i[2] = {0.f, 0.f};
    float o[8][4];
#pragma unroll
    for (int nt = 0; nt < 8; nt++)
#pragma unroll
        for (int r = 0; r < 4; r++) o[nt][r] = 0.f;

    const int nkt = 2 * qt + 2;

    for (int kt = 0; kt < nkt; kt++) {
        const int st = kt & 1;
        const int k0 = kt * 64;

        __syncthreads();   // all warps done reading stage st (2 iters ago)
        if (kt + 1 < nkt) {
            load_kv(kt + 1, st ^ 1);
            cp_commit();
            cp_wait<1>();
        } else {
            cp_wait<0>();
        }
        __syncthreads();   // stage st (and Q on iter 0) visible

        const float* Kc = Ks  + st * FT;
        const float* Vc = Vts + st * FT;

        // S = Q K^T
        float sc[8][4];
#pragma unroll
        for (int nt = 0; nt < 8; nt++)
#pragma unroll
            for (int r = 0; r < 4; r++) sc[nt][r] = 0.f;
#pragma unroll
        for (int kk = 0; kk < 8; kk++) {
            const int kb = kk * 8 + 2 * t;
            uint2 qlo = *(const uint2*)&Qs[(m0 + g)     * FS + kb];
            uint2 qhi = *(const uint2*)&Qs[(m0 + g + 8) * FS + kb];
#pragma unroll
            for (int nt = 0; nt < 8; nt++) {
                uint2 kb2 = *(const uint2*)&Kc[(nt * 8 + g) * FS + kb];
                mma_tf32(sc[nt], qlo.x, qhi.x, qlo.y, qhi.y, kb2.x, kb2.y);
            }
        }

        // Causal mask
        if (k0 + 63 > q0 + m0) {
#pragma unroll
            for (int nt = 0; nt < 8; nt++)
#pragma unroll
                for (int r = 0; r < 4; r++) {
                    int row = q0 + m0 + g + (r >> 1) * 8;
                    int col = k0 + nt * 8 + 2 * t + (r & 1);
                    if (col > row) sc[nt][r] = -1e30f;
                }
        }

        // Online softmax
#pragma unroll
        for (int rr = 0; rr < 2; rr++) {
            float tm = -INFINITY;
#pragma unroll
            for (int nt = 0; nt < 8; nt++)
                tm = fmaxf(tm, fmaxf(sc[nt][rr * 2], sc[nt][rr * 2 + 1]));
            tm = fmaxf(tm, __shfl_xor_sync(0xffffffffu, tm, 1));
            tm = fmaxf(tm, __shfl_xor_sync(0xffffffffu, tm, 2));
            float mn   = fmaxf(m_i[rr], tm);
            float corr = __expf(m_i[rr] - mn);
            float rs = 0.f;
#pragma unroll
            for (int nt = 0; nt < 8; nt++) {
                float p0 = __expf(sc[nt][rr * 2]     - mn);
                float p1 = __expf(sc[nt][rr * 2 + 1] - mn);
                sc[nt][rr * 2]     = p0;
                sc[nt][rr * 2 + 1] = p1;
                rs += p0 + p1;
            }
            rs += __shfl_xor_sync(0xffffffffu, rs, 1);
            rs += __shfl_xor_sync(0xffffffffu, rs, 2);
            l_i[rr] = l_i[rr] * corr + rs;
            m_i[rr] = mn;
#pragma unroll
            for (int nt = 0; nt < 8; nt++) {
                o[nt][rr * 2]     *= corr;
                o[nt][rr * 2 + 1] *= corr;
            }
        }

        // Round P; C-fragment IS the PV A-fragment (with Vt plain layout)
#pragma unroll
        for (int nt = 0; nt < 8; nt++)
#pragma unroll
            for (int r = 0; r < 4; r++) sc[nt][r] = round_tf(sc[nt][r]);

        // O += P @ V
#pragma unroll
        for (int kk = 0; kk < 8; kk++) {
            const int kb = kk * 8 + 2 * t;
            uint32_t a0 = __float_as_uint(sc[kk][0]);
            uint32_t a1 = __float_as_uint(sc[kk][2]);
            uint32_t a2 = __float_as_uint(sc[kk][1]);
            uint32_t a3 = __float_as_uint(sc[kk][3]);
#pragma unroll
            for (int nt = 0; nt < 8; nt++) {
                uint2 vB = *(const uint2*)&Vc[(nt * 8 + g) * FS + kb];
                mma_tf32(o[nt], a0, a1, a2, a3, vB.x, vB.y);
            }
        }
    }

    // Epilogue: ctx rounded to tf32 (feeds outproj A operand)
    const int b_ = bh >> 4;
    const int h  = bh & 15;
#pragma unroll
    for (int rr = 0; rr < 2; rr++) {
        int   q   = q0 + m0 + g + rr * 8;
        float inv = 1.f / l_i[rr];
#pragma unroll
        for (int nt = 0; nt < 8; nt++) {
            float2 rv = make_float2(round_tf(o[nt][rr * 2] * inv),
                                    round_tf(o[nt][rr * 2 + 1] * inv));
            *(float2*)&g_ctx[((size_t)(b_ * T_ + q)) * D_ + h * DK_ + nt * 8 + 2 * t] = rv;
        }
        if (t == 0) {
            g_m[(size_t)bh * T_ + q] = m_i[rr];
            g_l[(size_t)bh * T_ + q] = l_i[rr];
        }
    }
}

// ---------------------------------------------------------------------------
// Attn writeout: 256 threads, q-tile 128, kv-tile 64, K double-buffered.
// ---------------------------------------------------------------------------
constexpr int AO_SMEM_BYTES = (128 * FS + 2 * FT) * 4;  // 73728

__global__ __launch_bounds__(256) void attn_out_kernel(float* __restrict__ attn_base)
{
    extern __shared__ float asm_[];
    float* Qs = asm_;                 // [128][FS]
    float* Ks = asm_ + 128 * FS;      // [2][64][FS]

    const int tid  = threadIdx.x;
    const int wid  = tid >> 5;
    const int lane = tid & 31;
    const int g    = lane >> 2;
    const int t    = lane & 3;
    const int qt   = gridDim.x - 1 - blockIdx.x;
    const int bh   = blockIdx.y;
    const int q0   = qt * 128;
    const int m0   = wid * 16;

    const float* Qg   = g_Q + (size_t)bh * T_ * DK_;
    const float* Kg   = g_K + (size_t)bh * T_ * DK_;
    float*       attn = attn_base + (size_t)bh * T_ * T_;

    const int nct = 2 * qt + 2;

    auto load_k = [&](int kt_, int st) {
        const float* Kp = Kg + (size_t)kt_ * 64 * DK_;
        float* Kd = Ks + st * FT;
#pragma unroll
        for (int l = 0; l < 4; l++) {
            int idx = tid + l * 256;
            int r   = idx >> 4;
            int c4  = (idx & 15) * 4;
            cp_async16(&Kd[r * FS + c4], &Kp[(size_t)r * DK_ + c4]);
        }
    };

#pragma unroll
    for (int l = 0; l < 8; l++) {
        int idx = tid + l * 256;
        int r   = idx >> 4;
        int c4  = (idx & 15) * 4;
        cp_async16(&Qs[r * FS + c4], &Qg[(size_t)(q0 + r) * DK_ + c4]);
    }
    load_k(0, 0);
    cp_commit();

    // Masked region zeros
    {
        const int zc = T_ - nct * 64;
        if (zc > 0) {
            const int zc4 = zc >> 2;
            float4 z = make_float4(0.f, 0.f, 0.f, 0.f);
            for (int i = tid; i < 128 * zc4; i += 256) {
                int r  = i / zc4;
                int c4 = (i - r * zc4) * 4;
                *(float4*)&attn[(size_t)(q0 + r) * T_ + nct * 64 + c4] = z;
            }
        }
    }

    float mrow[2], linv[2];
#pragma unroll
    for (int rr = 0; rr < 2; rr++) {
        int q = q0 + m0 + g + rr * 8;
        mrow[rr] = g_m[(size_t)bh * T_ + q];
        linv[rr] = 1.f / g_l[(size_t)bh * T_ + q];
    }

    for (int kt = 0; kt < nct; kt++) {
        const int st = kt & 1;
        const int k0 = kt * 64;

        __syncthreads();
        if (kt + 1 < nct) {
            load_k(kt + 1, st ^ 1);
            cp_commit();
            cp_wait<1>();
        } else {
            cp_wait<0>();
        }
        __syncthreads();

        const float* Kc = Ks + st * FT;

        float sc[8][4];
#pragma unroll
        for (int nt = 0; nt < 8; nt++)
#pragma unroll
            for (int r = 0; r < 4; r++) sc[nt][r] = 0.f;
#pragma unroll
        for (int kk = 0; kk < 8; kk++) {
            const int kb = kk * 8 + 2 * t;
            uint2 qlo = *(const uint2*)&Qs[(m0 + g)     * FS + kb];
            uint2 qhi = *(const uint2*)&Qs[(m0 + g + 8) * FS + kb];
#pragma unroll
            for (int nt = 0; nt < 8; nt++) {
                uint2 kb2 = *(const uint2*)&Kc[(nt * 8 + g) * FS + kb];
                mma_tf32(sc[nt], qlo.x, qhi.x, qlo.y, qhi.y, kb2.x, kb2.y);
            }
        }

#pragma unroll
        for (int rr = 0; rr < 2; rr++) {
            int q = q0 + m0 + g + rr * 8;
#pragma unroll
            for (int nt = 0; nt < 8; nt++) {
                int col = k0 + nt * 8 + 2 * t;
                float p0 = (col     <= q) ? __expf(sc[nt][rr * 2]     - mrow[rr]) * linv[rr] : 0.f;
                float p1 = (col + 1 <= q) ? __expf(sc[nt][rr * 2 + 1] - mrow[rr]) * linv[rr] : 0.f;
                *(float2*)&attn[(size_t)q * T_ + col] = make_float2(p0, p1);
            }
        }
    }
}

// ---------------------------------------------------------------------------
extern "C" void kernel_launch(void* const* d_in, const int* in_sizes, int n_in,
                              void* d_out, int out_size)
{
    (void)in_sizes; (void)n_in; (void)out_size;
    const float* q_inp = (const float*)d_in[0];
    const float* k_inp = (const float*)d_in[1];
    const float* v_inp = (const float*)d_in[2];
    const float* Wq = (const float*)d_in[4];
    const float* bq = (const float*)d_in[5];
    const float* Wk = (const float*)d_in[6];
    const float* bk = (const float*)d_in[7];
    const float* Wv = (const float*)d_in[8];
    const float* bv = (const float*)d_in[9];
    const float* Wo = (const float*)d_in[10];
    const float* bo = (const float*)d_in[11];
    float* out = (float*)d_out;

    static cudaStream_t s2 = nullptr;
    static cudaEvent_t  e1 = nullptr, e2 = nullptr;
    if (!s2) {
        cudaStreamCreateWithFlags(&s2, cudaStreamNonBlocking);
        cudaEventCreateWithFlags(&e1, cudaEventDisableTiming);
        cudaEventCreateWithFlags(&e2, cudaEventDisableTiming);
        cudaFuncSetAttribute(qkv_kernel,      cudaFuncAttributeMaxDynamicSharedMemorySize, GEMM_SMEM_BYTES);
        cudaFuncSetAttribute(outproj_kernel,  cudaFuncAttributeMaxDynamicSharedMemorySize, GEMM_SMEM_BYTES);
        cudaFuncSetAttribute(flash_kernel,    cudaFuncAttributeMaxDynamicSharedMemorySize, FLASH_SMEM_BYTES);
        cudaFuncSetAttribute(attn_out_kernel, cudaFuncAttributeMaxDynamicSharedMemorySize, AO_SMEM_BYTES);
    }

    prep_x_kernel<<<dim3(XN / (4 * 256), 3), 256>>>(q_inp, k_inp, v_inp);
    prep_w_kernel<<<dim3(16, 16, 4), 256>>>(Wq, Wk, Wv, Wo, bq);
    qkv_kernel<<<dim3(8, 32, 3), 128, GEMM_SMEM_BYTES>>>(bk, bv);
    flash_kernel<<<dim3(16, 32), 256, FLASH_SMEM_BYTES>>>();

    // Fork: attn writeout on s2, output projection on the main stream.
    cudaEventRecord(e1, 0);
    cudaStreamWaitEvent(s2, e1, 0);
    attn_out_kernel<<<dim3(16, 32), 256, AO_SMEM_BYTES, s2>>>(out + OUT_ELEMS);
    outproj_kernel<<<dim3(8, 32), 128, GEMM_SMEM_BYTES>>>(bo, out);
    cudaEventRecord(e2, s2);
    cudaStreamWaitEvent(0, e2, 0);
}